// round 5
// baseline (speedup 1.0000x reference)
#include <cuda_runtime.h>
#include <cuda_bf16.h>
#include <math.h>
#include <stdint.h>

// Problem dims
#define BATCH   4096
#define D_IN    192
#define D_HID   512
#define D_OUT   128
#define N2      8192            // 2*BATCH
#define TEMP_INV 2.0f           // 1/0.5
#define BN_EPS   1e-5f

// ---------------- scratch (device globals; no allocation allowed) ----------
__device__ float g_y[N2 * D_HID];          // 16 MB: pre-BN activations
__device__ float g_bn_scale[2 * D_HID];
__device__ float g_bn_bias[2 * D_HID];
__device__ float g_zraw[N2 * D_OUT];       // 4 MB
__device__ float g_z[N2 * D_OUT];          // 4 MB (L2-normalized, fp32)
__device__ __nv_bfloat16 g_zh[N2 * D_OUT]; // 2 MB (bf16 copy for sim GEMM)
__device__ float g_partial_r[64 * N2];     // 2 MB: row-sums, slot bj
__device__ float g_partial_c[64 * N2];     // 2 MB: col-sums, slot bi
__device__ float g_rowloss[N2];
__device__ float g_pos[N2];                // positive-pair sim (fp32 exact, /T)

// ============================================================================
// MMA helpers (legacy warp-level mma.sync — plain PTX, works on sm_103 target)
// ============================================================================
__device__ __forceinline__ float to_tf32(float x) {
    float r;
    asm("cvt.rna.tf32.f32 %0, %1;" : "=f"(r) : "f"(x));
    return r;
}
__device__ __forceinline__ void mma_tf32(float* c, const uint32_t* a, const uint32_t* b)
{
    asm volatile(
        "mma.sync.aligned.m16n8k8.row.col.f32.tf32.tf32.f32 "
        "{%0,%1,%2,%3}, {%4,%5,%6,%7}, {%8,%9}, {%0,%1,%2,%3};"
        : "+f"(c[0]), "+f"(c[1]), "+f"(c[2]), "+f"(c[3])
        : "r"(a[0]), "r"(a[1]), "r"(a[2]), "r"(a[3]), "r"(b[0]), "r"(b[1]));
}
__device__ __forceinline__ void mma_bf16(float* c, const uint32_t* a, const uint32_t* b)
{
    asm volatile(
        "mma.sync.aligned.m16n8k16.row.col.f32.bf16.bf16.f32 "
        "{%0,%1,%2,%3}, {%4,%5,%6,%7}, {%8,%9}, {%0,%1,%2,%3};"
        : "+f"(c[0]), "+f"(c[1]), "+f"(c[2]), "+f"(c[3])
        : "r"(a[0]), "r"(a[1]), "r"(a[2]), "r"(a[3]), "r"(b[0]), "r"(b[1]));
}

// ============================================================================
// GEMM1 (tf32): y = X @ W1^T + b1.  M=8192, N=512, K=192
// Block 256 thr (8 warps, 4 row x 2 col), tile 128x64, BK=32.
// ============================================================================
#define G1_AS 36    // padded stride (floats)
__global__ __launch_bounds__(256) void gemm1_kernel(
    const float* __restrict__ h1, const float* __restrict__ h2,
    const float* __restrict__ W1, const float* __restrict__ b1)
{
    __shared__ float As[128][G1_AS];
    __shared__ float Bs[64][G1_AS];
    const int tid  = threadIdx.x;
    const int wid  = tid >> 5, lane = tid & 31;
    const int g    = lane >> 2, tq = lane & 3;
    const int wr   = (wid >> 1) * 32;
    const int wc   = (wid & 1) * 32;
    const int row0 = blockIdx.x * 128;
    const int col0 = blockIdx.y * 64;
    const float* A = (row0 < BATCH) ? h1 : h2;
    const int arow0 = (row0 < BATCH) ? row0 : (row0 - BATCH);

    float acc[2][4][4] = {};

    for (int kt = 0; kt < D_IN; kt += 32) {
        const int kt4 = kt >> 2;
        #pragma unroll
        for (int it = 0; it < 4; it++) {
            int idx = tid + it * 256;
            int r = idx >> 3, c = idx & 7;
            float4 v = ((const float4*)A)[(arow0 + r) * 48 + kt4 + c];
            float* d = &As[r][c * 4];
            d[0] = to_tf32(v.x); d[1] = to_tf32(v.y);
            d[2] = to_tf32(v.z); d[3] = to_tf32(v.w);
        }
        #pragma unroll
        for (int it = 0; it < 2; it++) {
            int idx = tid + it * 256;
            int r = idx >> 3, c = idx & 7;
            float4 v = ((const float4*)W1)[(col0 + r) * 48 + kt4 + c];
            float* d = &Bs[r][c * 4];
            d[0] = to_tf32(v.x); d[1] = to_tf32(v.y);
            d[2] = to_tf32(v.z); d[3] = to_tf32(v.w);
        }
        __syncthreads();
        #pragma unroll
        for (int kk = 0; kk < 4; kk++) {
            uint32_t a[2][4], b[4][2];
            #pragma unroll
            for (int mi = 0; mi < 2; mi++) {
                const uint32_t* ap = (const uint32_t*)&As[wr + mi * 16 + g][kk * 8 + tq];
                a[mi][0] = ap[0];
                a[mi][1] = ap[8 * G1_AS];
                a[mi][2] = ap[4];
                a[mi][3] = ap[8 * G1_AS + 4];
            }
            #pragma unroll
            for (int ni = 0; ni < 4; ni++) {
                const uint32_t* bp = (const uint32_t*)&Bs[wc + ni * 8 + g][kk * 8 + tq];
                b[ni][0] = bp[0];
                b[ni][1] = bp[4];
            }
            #pragma unroll
            for (int mi = 0; mi < 2; mi++)
                #pragma unroll
                for (int ni = 0; ni < 4; ni++)
                    mma_tf32(acc[mi][ni], a[mi], b[ni]);
        }
        __syncthreads();
    }
    #pragma unroll
    for (int mi = 0; mi < 2; mi++) {
        const int r0 = row0 + wr + mi * 16 + g;
        #pragma unroll
        for (int ni = 0; ni < 4; ni++) {
            const int c0 = col0 + wc + ni * 8 + tq * 2;
            g_y[r0 * D_HID + c0]           = acc[mi][ni][0] + b1[c0];
            g_y[r0 * D_HID + c0 + 1]       = acc[mi][ni][1] + b1[c0 + 1];
            g_y[(r0 + 8) * D_HID + c0]     = acc[mi][ni][2] + b1[c0];
            g_y[(r0 + 8) * D_HID + c0 + 1] = acc[mi][ni][3] + b1[c0 + 1];
        }
    }
}

// ============================================================================
// BN stats
// ============================================================================
__global__ void bn_stats_kernel(const float* __restrict__ gamma,
                                const float* __restrict__ beta)
{
    const int c = blockIdx.x * 64 + threadIdx.x;
    const int head = blockIdx.y;
    const float* Y = g_y + head * BATCH * D_HID;
    float s = 0.f, sq = 0.f;
    for (int r = threadIdx.y; r < BATCH; r += 4) {
        float v = Y[r * D_HID + c];
        s += v; sq += v * v;
    }
    __shared__ float sh_s[4][64], sh_q[4][64];
    sh_s[threadIdx.y][threadIdx.x] = s;
    sh_q[threadIdx.y][threadIdx.x] = sq;
    __syncthreads();
    if (threadIdx.y == 0) {
        s  = sh_s[0][threadIdx.x] + sh_s[1][threadIdx.x] + sh_s[2][threadIdx.x] + sh_s[3][threadIdx.x];
        sq = sh_q[0][threadIdx.x] + sh_q[1][threadIdx.x] + sh_q[2][threadIdx.x] + sh_q[3][threadIdx.x];
        float mean = s * (1.0f / BATCH);
        float var  = sq * (1.0f / BATCH) - mean * mean;
        float a = gamma[c] * rsqrtf(var + BN_EPS);
        g_bn_scale[head * D_HID + c] = a;
        g_bn_bias[head * D_HID + c]  = beta[c] - mean * a;
    }
}

// ============================================================================
// GEMM2 (tf32): zraw = relu(bn(y)) @ W2^T + b2.  M=8192, N=128, K=512
// ============================================================================
__global__ __launch_bounds__(256) void gemm2_kernel(
    const float* __restrict__ W2, const float* __restrict__ b2)
{
    __shared__ float As[128][G1_AS];
    __shared__ float Bs[64][G1_AS];
    const int tid  = threadIdx.x;
    const int wid  = tid >> 5, lane = tid & 31;
    const int g    = lane >> 2, tq = lane & 3;
    const int wr   = (wid >> 1) * 32;
    const int wc   = (wid & 1) * 32;
    const int row0 = blockIdx.x * 128;
    const int col0 = blockIdx.y * 64;
    const int head = row0 >> 12;
    const float* sc = g_bn_scale + head * D_HID;
    const float* bi = g_bn_bias  + head * D_HID;

    float acc[2][4][4] = {};

    for (int kt = 0; kt < D_HID; kt += 32) {
        const int kt4 = kt >> 2;
        #pragma unroll
        for (int it = 0; it < 4; it++) {
            int idx = tid + it * 256;
            int r = idx >> 3, c = idx & 7;
            float4 v = ((const float4*)g_y)[(row0 + r) * 128 + kt4 + c];
            float4 s4 = ((const float4*)sc)[kt4 + c];
            float4 o4 = ((const float4*)bi)[kt4 + c];
            float* d = &As[r][c * 4];
            d[0] = to_tf32(fmaxf(fmaf(v.x, s4.x, o4.x), 0.f));
            d[1] = to_tf32(fmaxf(fmaf(v.y, s4.y, o4.y), 0.f));
            d[2] = to_tf32(fmaxf(fmaf(v.z, s4.z, o4.z), 0.f));
            d[3] = to_tf32(fmaxf(fmaf(v.w, s4.w, o4.w), 0.f));
        }
        #pragma unroll
        for (int it = 0; it < 2; it++) {
            int idx = tid + it * 256;
            int r = idx >> 3, c = idx & 7;
            float4 v = ((const float4*)W2)[(col0 + r) * 128 + kt4 + c];
            float* d = &Bs[r][c * 4];
            d[0] = to_tf32(v.x); d[1] = to_tf32(v.y);
            d[2] = to_tf32(v.z); d[3] = to_tf32(v.w);
        }
        __syncthreads();
        #pragma unroll
        for (int kk = 0; kk < 4; kk++) {
            uint32_t a[2][4], b[4][2];
            #pragma unroll
            for (int mi = 0; mi < 2; mi++) {
                const uint32_t* ap = (const uint32_t*)&As[wr + mi * 16 + g][kk * 8 + tq];
                a[mi][0] = ap[0];
                a[mi][1] = ap[8 * G1_AS];
                a[mi][2] = ap[4];
                a[mi][3] = ap[8 * G1_AS + 4];
            }
            #pragma unroll
            for (int ni = 0; ni < 4; ni++) {
                const uint32_t* bp = (const uint32_t*)&Bs[wc + ni * 8 + g][kk * 8 + tq];
                b[ni][0] = bp[0];
                b[ni][1] = bp[4];
            }
            #pragma unroll
            for (int mi = 0; mi < 2; mi++)
                #pragma unroll
                for (int ni = 0; ni < 4; ni++)
                    mma_tf32(acc[mi][ni], a[mi], b[ni]);
        }
        __syncthreads();
    }
    #pragma unroll
    for (int mi = 0; mi < 2; mi++) {
        const int r0 = row0 + wr + mi * 16 + g;
        #pragma unroll
        for (int ni = 0; ni < 4; ni++) {
            const int c0 = col0 + wc + ni * 8 + tq * 2;
            g_zraw[r0 * D_OUT + c0]           = acc[mi][ni][0] + b2[c0];
            g_zraw[r0 * D_OUT + c0 + 1]       = acc[mi][ni][1] + b2[c0 + 1];
            g_zraw[(r0 + 8) * D_OUT + c0]     = acc[mi][ni][2] + b2[c0];
            g_zraw[(r0 + 8) * D_OUT + c0 + 1] = acc[mi][ni][3] + b2[c0 + 1];
        }
    }
}

// ============================================================================
// L2 normalize; emit fp32 (d_out + g_z) and bf16 (g_zh)
// ============================================================================
__global__ void norm_kernel(float* __restrict__ out)
{
    const int row  = blockIdx.x * 8 + (threadIdx.x >> 5);
    const int lane = threadIdx.x & 31;
    const float4 v = ((const float4*)(g_zraw + row * D_OUT))[lane];
    float s = v.x * v.x + v.y * v.y + v.z * v.z + v.w * v.w;
    #pragma unroll
    for (int o = 16; o; o >>= 1) s += __shfl_xor_sync(0xffffffffu, s, o);
    const float inv = 1.0f / fmaxf(sqrtf(s), 1e-12f);
    float4 z = make_float4(v.x * inv, v.y * inv, v.z * inv, v.w * inv);
    ((float4*)(g_z + row * D_OUT))[lane] = z;
    __nv_bfloat162* zh2 = (__nv_bfloat162*)(g_zh + row * D_OUT);
    zh2[lane * 2 + 0] = __nv_bfloat162(__float2bfloat16(z.x), __float2bfloat16(z.y));
    zh2[lane * 2 + 1] = __nv_bfloat162(__float2bfloat16(z.z), __float2bfloat16(z.w));
    float* o4 = out + 1 + row * D_OUT + lane * 4;   // +1 breaks 16B align
    o4[0] = z.x; o4[1] = z.y; o4[2] = z.z; o4[3] = z.w;
}

// ============================================================================
// pos[i] = (z1_i . z2_i) / T in exact fp32 (one warp per pair)
// ============================================================================
__global__ void pos_kernel()
{
    const int i    = blockIdx.x * 8 + (threadIdx.x >> 5);
    const int lane = threadIdx.x & 31;
    const float4 a = ((const float4*)(g_z + i * D_OUT))[lane];
    const float4 b = ((const float4*)(g_z + (i + BATCH) * D_OUT))[lane];
    float s = a.x * b.x + a.y * b.y + a.z * b.z + a.w * b.w;
    #pragma unroll
    for (int o = 16; o; o >>= 1) s += __shfl_xor_sync(0xffffffffu, s, o);
    if (lane == 0) {
        float p = s * TEMP_INV;
        g_pos[i] = p;
        g_pos[i + BATCH] = p;
    }
}

// ============================================================================
// Symmetric sim: grid (64,64), only bi<=bj tiles computed (2080 of 4096).
// Per tile: row-sums -> g_partial_r[bj][rows of bi],
//           col-sums -> g_partial_c[bi][cols of bj] (0 on diagonal tiles).
// Block 256 thr (8 warps, 2 row-groups x 4 col-groups), tile 128x128, K=128.
// ============================================================================
#define SIM_TILE_STRIDE 136
#define SIM_SMEM_BYTES  (2 * 128 * SIM_TILE_STRIDE * 2)   // 69632

__global__ __launch_bounds__(256) void sim_kernel()
{
    const int bi = blockIdx.x, bj = blockIdx.y;
    if (bj < bi) return;

    extern __shared__ __nv_bfloat16 smem_bf[];
    __nv_bfloat16* As = smem_bf;
    __nv_bfloat16* Bs = smem_bf + 128 * SIM_TILE_STRIDE;

    const int tid  = threadIdx.x;
    const int wid  = tid >> 5, lane = tid & 31;
    const int g    = lane >> 2, tq = lane & 3;
    const int wr   = (wid >> 2) * 64;                  // warp row base (0/64)
    const int wn   = wid & 3;                          // warp col group
    const int wc   = wn * 32;
    const int row0 = bi * 128;
    const int col0 = bj * 128;
    const bool diag = (bi == bj);

    // Load A and B tiles (row stride 17 uint4 = 136 bf16)
    {
        const uint4* srcA = (const uint4*)(g_zh + row0 * D_OUT);
        const uint4* srcB = (const uint4*)(g_zh + col0 * D_OUT);
        uint4* dA = (uint4*)As;
        uint4* dB = (uint4*)Bs;
        for (int idx = tid; idx < 2048; idx += 256) {
            int r = idx >> 4, c = idx & 15;
            dA[r * 17 + c] = srcA[idx];
            dB[r * 17 + c] = srcB[idx];
        }
    }
    __syncthreads();

    float acc[4][4][4] = {};
    #pragma unroll
    for (int kk = 0; kk < 128; kk += 16) {
        uint32_t a[4][4], b[4][2];
        #pragma unroll
        for (int mi = 0; mi < 4; mi++) {
            const __nv_bfloat16* ap = As + (wr + mi * 16 + g) * SIM_TILE_STRIDE + kk + tq * 2;
            a[mi][0] = *(const uint32_t*)ap;
            a[mi][1] = *(const uint32_t*)(ap + 8 * SIM_TILE_STRIDE);
            a[mi][2] = *(const uint32_t*)(ap + 8);
            a[mi][3] = *(const uint32_t*)(ap + 8 * SIM_TILE_STRIDE + 8);
        }
        #pragma unroll
        for (int ni = 0; ni < 4; ni++) {
            const __nv_bfloat16* bp = Bs + (wc + ni * 8 + g) * SIM_TILE_STRIDE + kk + tq * 2;
            b[ni][0] = *(const uint32_t*)bp;
            b[ni][1] = *(const uint32_t*)(bp + 8);
        }
        #pragma unroll
        for (int mi = 0; mi < 4; mi++)
            #pragma unroll
            for (int ni = 0; ni < 4; ni++)
                mma_bf16(acc[mi][ni], a[mi], b[ni]);
    }

    // Epilogue: exp(2*sim); zero diagonal on diag tiles; row + col partials
    float rowAcc[4][2] = {};
    float colAcc[4][2] = {};
    #pragma unroll
    for (int mi = 0; mi < 4; mi++) {
        const int lr0 = wr + mi * 16 + g;     // local row in tile
        const int lr1 = lr0 + 8;
        #pragma unroll
        for (int ni = 0; ni < 4; ni++) {
            const int lj0 = wc + ni * 8 + tq * 2;  // local col in tile
            float e00 = __expf(2.0f * acc[mi][ni][0]);
            float e01 = __expf(2.0f * acc[mi][ni][1]);
            float e10 = __expf(2.0f * acc[mi][ni][2]);
            float e11 = __expf(2.0f * acc[mi][ni][3]);
            if (diag) {
                if (lj0     == lr0) e00 = 0.f;
                if (lj0 + 1 == lr0) e01 = 0.f;
                if (lj0     == lr1) e10 = 0.f;
                if (lj0 + 1 == lr1) e11 = 0.f;
            }
            rowAcc[mi][0] += e00 + e01;
            rowAcc[mi][1] += e10 + e11;
            colAcc[ni][0] += e00 + e10;
            colAcc[ni][1] += e01 + e11;
        }
    }

    // ---- row reduce: over tq lanes (XOR 1,2), then over wn warp groups ----
    #pragma unroll
    for (int mi = 0; mi < 4; mi++)
        #pragma unroll
        for (int h = 0; h < 2; h++) {
            float s = rowAcc[mi][h];
            s += __shfl_xor_sync(0xffffffffu, s, 1);
            s += __shfl_xor_sync(0xffffffffu, s, 2);
            rowAcc[mi][h] = s;
        }
    // ---- col reduce: over g lanes (XOR 4,8,16) ----
    #pragma unroll
    for (int ni = 0; ni < 4; ni++)
        #pragma unroll
        for (int h = 0; h < 2; h++) {
            float s = colAcc[ni][h];
            s += __shfl_xor_sync(0xffffffffu, s, 4);
            s += __shfl_xor_sync(0xffffffffu, s, 8);
            s += __shfl_xor_sync(0xffffffffu, s, 16);
            colAcc[ni][h] = s;
        }

    __syncthreads();                         // done with As/Bs; reuse as buffers
    float* red_r = (float*)smem_bf;          // [4 wn][128 rows]
    float* red_c = red_r + 512;              // [8 wid][32 cols]
    if (tq == 0) {
        #pragma unroll
        for (int mi = 0; mi < 4; mi++) {
            red_r[wn * 128 + wr + mi * 16 + g]     = rowAcc[mi][0];
            red_r[wn * 128 + wr + mi * 16 + g + 8] = rowAcc[mi][1];
        }
    }
    if (g == 0) {                            // lanes 0..3 (lane == tq)
        #pragma unroll
        for (int ni = 0; ni < 4; ni++) {
            red_c[wid * 32 + ni * 8 + tq * 2]     = colAcc[ni][0];
            red_c[wid * 32 + ni * 8 + tq * 2 + 1] = colAcc[ni][1];
        }
    }
    __syncthreads();
    if (tid < 128) {
        float rs = red_r[tid] + red_r[128 + tid] + red_r[256 + tid] + red_r[384 + tid];
        g_partial_r[bj * N2 + row0 + tid] = rs;

        int wgrp = tid >> 5, jl = tid & 31;
        float cs = diag ? 0.f : (red_c[wgrp * 32 + jl] + red_c[(wgrp + 4) * 32 + jl]);
        g_partial_c[bi * N2 + col0 + tid] = cs;
    }
}

// ============================================================================
// rowloss[i] = log( sum of written partial slots ) - pos[i]
// Row i (block b=i>>7): r[x][i] for x in [b,63], c[x][i] for x in [0,b].
// ============================================================================
__global__ void rowloss_kernel()
{
    const int i = blockIdx.x * 128 + threadIdx.x;
    const int b = i >> 7;
    float se = 0.f;
    for (int x = b; x < 64; x++) se += g_partial_r[x * N2 + i];
    for (int x = 0; x <= b; x++) se += g_partial_c[x * N2 + i];
    g_rowloss[i] = logf(se) - g_pos[i];
}

// ============================================================================
// loss = mean(rowloss)
// ============================================================================
__global__ void loss_kernel(float* __restrict__ out)
{
    __shared__ float sh[256];
    float s = 0.f;
    for (int i = threadIdx.x; i < N2; i += 256) s += g_rowloss[i];
    sh[threadIdx.x] = s;
    __syncthreads();
    for (int o = 128; o; o >>= 1) {
        if (threadIdx.x < o) sh[threadIdx.x] += sh[threadIdx.x + o];
        __syncthreads();
    }
    if (threadIdx.x == 0) out[0] = sh[0] * (1.0f / N2);
}

// ============================================================================
extern "C" void kernel_launch(void* const* d_in, const int* in_sizes, int n_in,
                              void* d_out, int out_size)
{
    const float* h1    = (const float*)d_in[0];
    const float* h2    = (const float*)d_in[1];
    const float* W1    = (const float*)d_in[2];
    const float* b1    = (const float*)d_in[3];
    const float* gamma = (const float*)d_in[4];
    const float* beta  = (const float*)d_in[5];
    const float* W2    = (const float*)d_in[6];
    const float* b2    = (const float*)d_in[7];
    float* out = (float*)d_out;

    cudaFuncSetAttribute(sim_kernel, cudaFuncAttributeMaxDynamicSharedMemorySize,
                         SIM_SMEM_BYTES);

    gemm1_kernel<<<dim3(N2 / 128, D_HID / 64), 256>>>(h1, h2, W1, b1);
    bn_stats_kernel<<<dim3(D_HID / 64, 2), dim3(64, 4)>>>(gamma, beta);
    gemm2_kernel<<<dim3(N2 / 128, D_OUT / 64), 256>>>(W2, b2);
    norm_kernel<<<N2 / 8, 256>>>(out);
    pos_kernel<<<BATCH / 8, 256>>>();
    sim_kernel<<<dim3(64, 64), 256, SIM_SMEM_BYTES>>>();
    rowloss_kernel<<<N2 / 128, 128>>>();
    loss_kernel<<<1, 256>>>(out);
}

// round 6
// speedup vs baseline: 1.4834x; 1.4834x over previous
#include <cuda_runtime.h>
#include <cuda_bf16.h>
#include <math.h>
#include <stdint.h>

// Problem dims
#define BATCH   4096
#define D_IN    192
#define D_HID   512
#define D_OUT   128
#define N2      8192            // 2*BATCH
#define TEMP_INV 2.0f           // 1/0.5
#define BN_EPS   1e-5f

// Sim symmetric-tiling config: 64 row/col tile-blocks of 128; groups of 4 col tiles
#define SIM_GROUPS 544          // sum_{bi} ceil((64-bi)/4)
#define SIM_MAX_T  16           // max groups per row-panel

// ---------------- scratch (device globals; no allocation allowed) ----------
__device__ float g_y[N2 * D_HID];          // 16 MB: pre-BN activations
__device__ float g_bn_scale[2 * D_HID];
__device__ float g_bn_bias[2 * D_HID];
__device__ float g_zraw[N2 * D_OUT];       // 4 MB
__device__ float g_z[N2 * D_OUT];          // 4 MB (L2-normalized, fp32)
__device__ __nv_bfloat16 g_zh[N2 * D_OUT]; // 2 MB (bf16 copy for sim GEMM)
__device__ float g_partial_r[SIM_MAX_T * N2];  // row-sums, slot = group idx t
__device__ float g_partial_c[64 * N2];         // col-sums, slot = bi
__device__ float g_rowloss[N2];
__device__ float g_pos[N2];                // positive-pair sim (fp32 exact, /T)

// ============================================================================
// MMA helpers (legacy warp-level mma.sync — plain PTX, works on sm_103 target)
// ============================================================================
__device__ __forceinline__ float to_tf32(float x) {
    float r;
    asm("cvt.rna.tf32.f32 %0, %1;" : "=f"(r) : "f"(x));
    return r;
}
__device__ __forceinline__ void mma_tf32(float* c, const uint32_t* a, const uint32_t* b)
{
    asm volatile(
        "mma.sync.aligned.m16n8k8.row.col.f32.tf32.tf32.f32 "
        "{%0,%1,%2,%3}, {%4,%5,%6,%7}, {%8,%9}, {%0,%1,%2,%3};"
        : "+f"(c[0]), "+f"(c[1]), "+f"(c[2]), "+f"(c[3])
        : "r"(a[0]), "r"(a[1]), "r"(a[2]), "r"(a[3]), "r"(b[0]), "r"(b[1]));
}
__device__ __forceinline__ void mma_bf16(float* c, const uint32_t* a, const uint32_t* b)
{
    asm volatile(
        "mma.sync.aligned.m16n8k16.row.col.f32.bf16.bf16.f32 "
        "{%0,%1,%2,%3}, {%4,%5,%6,%7}, {%8,%9}, {%0,%1,%2,%3};"
        : "+f"(c[0]), "+f"(c[1]), "+f"(c[2]), "+f"(c[3])
        : "r"(a[0]), "r"(a[1]), "r"(a[2]), "r"(a[3]), "r"(b[0]), "r"(b[1]));
}

// ============================================================================
// GEMM1 (tf32): y = X @ W1^T + b1.  M=8192, N=512, K=192
// ============================================================================
#define G1_AS 36    // padded stride (floats)
__global__ __launch_bounds__(256) void gemm1_kernel(
    const float* __restrict__ h1, const float* __restrict__ h2,
    const float* __restrict__ W1, const float* __restrict__ b1)
{
    __shared__ float As[128][G1_AS];
    __shared__ float Bs[64][G1_AS];
    const int tid  = threadIdx.x;
    const int wid  = tid >> 5, lane = tid & 31;
    const int g    = lane >> 2, tq = lane & 3;
    const int wr   = (wid >> 1) * 32;
    const int wc   = (wid & 1) * 32;
    const int row0 = blockIdx.x * 128;
    const int col0 = blockIdx.y * 64;
    const float* A = (row0 < BATCH) ? h1 : h2;
    const int arow0 = (row0 < BATCH) ? row0 : (row0 - BATCH);

    float acc[2][4][4] = {};

    for (int kt = 0; kt < D_IN; kt += 32) {
        const int kt4 = kt >> 2;
        #pragma unroll
        for (int it = 0; it < 4; it++) {
            int idx = tid + it * 256;
            int r = idx >> 3, c = idx & 7;
            float4 v = ((const float4*)A)[(arow0 + r) * 48 + kt4 + c];
            float* d = &As[r][c * 4];
            d[0] = to_tf32(v.x); d[1] = to_tf32(v.y);
            d[2] = to_tf32(v.z); d[3] = to_tf32(v.w);
        }
        #pragma unroll
        for (int it = 0; it < 2; it++) {
            int idx = tid + it * 256;
            int r = idx >> 3, c = idx & 7;
            float4 v = ((const float4*)W1)[(col0 + r) * 48 + kt4 + c];
            float* d = &Bs[r][c * 4];
            d[0] = to_tf32(v.x); d[1] = to_tf32(v.y);
            d[2] = to_tf32(v.z); d[3] = to_tf32(v.w);
        }
        __syncthreads();
        #pragma unroll
        for (int kk = 0; kk < 4; kk++) {
            uint32_t a[2][4], b[4][2];
            #pragma unroll
            for (int mi = 0; mi < 2; mi++) {
                const uint32_t* ap = (const uint32_t*)&As[wr + mi * 16 + g][kk * 8 + tq];
                a[mi][0] = ap[0];
                a[mi][1] = ap[8 * G1_AS];
                a[mi][2] = ap[4];
                a[mi][3] = ap[8 * G1_AS + 4];
            }
            #pragma unroll
            for (int ni = 0; ni < 4; ni++) {
                const uint32_t* bp = (const uint32_t*)&Bs[wc + ni * 8 + g][kk * 8 + tq];
                b[ni][0] = bp[0];
                b[ni][1] = bp[4];
            }
            #pragma unroll
            for (int mi = 0; mi < 2; mi++)
                #pragma unroll
                for (int ni = 0; ni < 4; ni++)
                    mma_tf32(acc[mi][ni], a[mi], b[ni]);
        }
        __syncthreads();
    }
    #pragma unroll
    for (int mi = 0; mi < 2; mi++) {
        const int r0 = row0 + wr + mi * 16 + g;
        #pragma unroll
        for (int ni = 0; ni < 4; ni++) {
            const int c0 = col0 + wc + ni * 8 + tq * 2;
            g_y[r0 * D_HID + c0]           = acc[mi][ni][0] + b1[c0];
            g_y[r0 * D_HID + c0 + 1]       = acc[mi][ni][1] + b1[c0 + 1];
            g_y[(r0 + 8) * D_HID + c0]     = acc[mi][ni][2] + b1[c0];
            g_y[(r0 + 8) * D_HID + c0 + 1] = acc[mi][ni][3] + b1[c0 + 1];
        }
    }
}

// ============================================================================
// BN stats
// ============================================================================
__global__ void bn_stats_kernel(const float* __restrict__ gamma,
                                const float* __restrict__ beta)
{
    const int c = blockIdx.x * 64 + threadIdx.x;
    const int head = blockIdx.y;
    const float* Y = g_y + head * BATCH * D_HID;
    float s = 0.f, sq = 0.f;
    for (int r = threadIdx.y; r < BATCH; r += 4) {
        float v = Y[r * D_HID + c];
        s += v; sq += v * v;
    }
    __shared__ float sh_s[4][64], sh_q[4][64];
    sh_s[threadIdx.y][threadIdx.x] = s;
    sh_q[threadIdx.y][threadIdx.x] = sq;
    __syncthreads();
    if (threadIdx.y == 0) {
        s  = sh_s[0][threadIdx.x] + sh_s[1][threadIdx.x] + sh_s[2][threadIdx.x] + sh_s[3][threadIdx.x];
        sq = sh_q[0][threadIdx.x] + sh_q[1][threadIdx.x] + sh_q[2][threadIdx.x] + sh_q[3][threadIdx.x];
        float mean = s * (1.0f / BATCH);
        float var  = sq * (1.0f / BATCH) - mean * mean;
        float a = gamma[c] * rsqrtf(var + BN_EPS);
        g_bn_scale[head * D_HID + c] = a;
        g_bn_bias[head * D_HID + c]  = beta[c] - mean * a;
    }
}

// ============================================================================
// GEMM2 (tf32): zraw = relu(bn(y)) @ W2^T + b2.  M=8192, N=128, K=512
// ============================================================================
__global__ __launch_bounds__(256) void gemm2_kernel(
    const float* __restrict__ W2, const float* __restrict__ b2)
{
    __shared__ float As[128][G1_AS];
    __shared__ float Bs[64][G1_AS];
    const int tid  = threadIdx.x;
    const int wid  = tid >> 5, lane = tid & 31;
    const int g    = lane >> 2, tq = lane & 3;
    const int wr   = (wid >> 1) * 32;
    const int wc   = (wid & 1) * 32;
    const int row0 = blockIdx.x * 128;
    const int col0 = blockIdx.y * 64;
    const int head = row0 >> 12;
    const float* sc = g_bn_scale + head * D_HID;
    const float* bi = g_bn_bias  + head * D_HID;

    float acc[2][4][4] = {};

    for (int kt = 0; kt < D_HID; kt += 32) {
        const int kt4 = kt >> 2;
        #pragma unroll
        for (int it = 0; it < 4; it++) {
            int idx = tid + it * 256;
            int r = idx >> 3, c = idx & 7;
            float4 v = ((const float4*)g_y)[(row0 + r) * 128 + kt4 + c];
            float4 s4 = ((const float4*)sc)[kt4 + c];
            float4 o4 = ((const float4*)bi)[kt4 + c];
            float* d = &As[r][c * 4];
            d[0] = to_tf32(fmaxf(fmaf(v.x, s4.x, o4.x), 0.f));
            d[1] = to_tf32(fmaxf(fmaf(v.y, s4.y, o4.y), 0.f));
            d[2] = to_tf32(fmaxf(fmaf(v.z, s4.z, o4.z), 0.f));
            d[3] = to_tf32(fmaxf(fmaf(v.w, s4.w, o4.w), 0.f));
        }
        #pragma unroll
        for (int it = 0; it < 2; it++) {
            int idx = tid + it * 256;
            int r = idx >> 3, c = idx & 7;
            float4 v = ((const float4*)W2)[(col0 + r) * 128 + kt4 + c];
            float* d = &Bs[r][c * 4];
            d[0] = to_tf32(v.x); d[1] = to_tf32(v.y);
            d[2] = to_tf32(v.z); d[3] = to_tf32(v.w);
        }
        __syncthreads();
        #pragma unroll
        for (int kk = 0; kk < 4; kk++) {
            uint32_t a[2][4], b[4][2];
            #pragma unroll
            for (int mi = 0; mi < 2; mi++) {
                const uint32_t* ap = (const uint32_t*)&As[wr + mi * 16 + g][kk * 8 + tq];
                a[mi][0] = ap[0];
                a[mi][1] = ap[8 * G1_AS];
                a[mi][2] = ap[4];
                a[mi][3] = ap[8 * G1_AS + 4];
            }
            #pragma unroll
            for (int ni = 0; ni < 4; ni++) {
                const uint32_t* bp = (const uint32_t*)&Bs[wc + ni * 8 + g][kk * 8 + tq];
                b[ni][0] = bp[0];
                b[ni][1] = bp[4];
            }
            #pragma unroll
            for (int mi = 0; mi < 2; mi++)
                #pragma unroll
                for (int ni = 0; ni < 4; ni++)
                    mma_tf32(acc[mi][ni], a[mi], b[ni]);
        }
        __syncthreads();
    }
    #pragma unroll
    for (int mi = 0; mi < 2; mi++) {
        const int r0 = row0 + wr + mi * 16 + g;
        #pragma unroll
        for (int ni = 0; ni < 4; ni++) {
            const int c0 = col0 + wc + ni * 8 + tq * 2;
            g_zraw[r0 * D_OUT + c0]           = acc[mi][ni][0] + b2[c0];
            g_zraw[r0 * D_OUT + c0 + 1]       = acc[mi][ni][1] + b2[c0 + 1];
            g_zraw[(r0 + 8) * D_OUT + c0]     = acc[mi][ni][2] + b2[c0];
            g_zraw[(r0 + 8) * D_OUT + c0 + 1] = acc[mi][ni][3] + b2[c0 + 1];
        }
    }
}

// ============================================================================
// L2 normalize; emit fp32 (d_out + g_z) and bf16 (g_zh)
// ============================================================================
__global__ void norm_kernel(float* __restrict__ out)
{
    const int row  = blockIdx.x * 8 + (threadIdx.x >> 5);
    const int lane = threadIdx.x & 31;
    const float4 v = ((const float4*)(g_zraw + row * D_OUT))[lane];
    float s = v.x * v.x + v.y * v.y + v.z * v.z + v.w * v.w;
    #pragma unroll
    for (int o = 16; o; o >>= 1) s += __shfl_xor_sync(0xffffffffu, s, o);
    const float inv = 1.0f / fmaxf(sqrtf(s), 1e-12f);
    float4 z = make_float4(v.x * inv, v.y * inv, v.z * inv, v.w * inv);
    ((float4*)(g_z + row * D_OUT))[lane] = z;
    __nv_bfloat162* zh2 = (__nv_bfloat162*)(g_zh + row * D_OUT);
    zh2[lane * 2 + 0] = __nv_bfloat162(__float2bfloat16(z.x), __float2bfloat16(z.y));
    zh2[lane * 2 + 1] = __nv_bfloat162(__float2bfloat16(z.z), __float2bfloat16(z.w));
    float* o4 = out + 1 + row * D_OUT + lane * 4;   // +1 breaks 16B align
    o4[0] = z.x; o4[1] = z.y; o4[2] = z.z; o4[3] = z.w;
}

// ============================================================================
// pos[i] = (z1_i . z2_i) / T in exact fp32 (one warp per pair)
// ============================================================================
__global__ void pos_kernel()
{
    const int i    = blockIdx.x * 8 + (threadIdx.x >> 5);
    const int lane = threadIdx.x & 31;
    const float4 a = ((const float4*)(g_z + i * D_OUT))[lane];
    const float4 b = ((const float4*)(g_z + (i + BATCH) * D_OUT))[lane];
    float s = a.x * b.x + a.y * b.y + a.z * b.z + a.w * b.w;
    #pragma unroll
    for (int o = 16; o; o >>= 1) s += __shfl_xor_sync(0xffffffffu, s, o);
    if (lane == 0) {
        float p = s * TEMP_INV;
        g_pos[i] = p;
        g_pos[i + BATCH] = p;
    }
}

// ============================================================================
// Symmetric sim, grouped: block = (row panel bi) x (group t of <=4 col tiles).
// 544 blocks, A loaded once per block. __launch_bounds__(256,2) pins 2/SM.
// Row partials accumulate in regs across group -> g_partial_r[t][rows of bi].
// Col partials written per tile -> g_partial_c[bi][cols of bj] (0 on diag).
// ============================================================================
#define SIM_TILE_STRIDE 136
// As + Bs + red_c staging (256 floats)
#define SIM_SMEM_BYTES  (2 * 128 * SIM_TILE_STRIDE * 2 + 1024)   // 70656

__global__ __launch_bounds__(256, 2) void sim_kernel()
{
    // Map 1-D block id -> (bi, t)
    int rem = blockIdx.x, bi = 0;
    for (;;) {
        int cnt = (64 - bi + 3) >> 2;
        if (rem < cnt) break;
        rem -= cnt; bi++;
    }
    const int bj0  = bi + rem * 4;
    const int jend = (bj0 + 4 < 64) ? bj0 + 4 : 64;

    extern __shared__ __nv_bfloat16 smem_bf[];
    __nv_bfloat16* As = smem_bf;
    __nv_bfloat16* Bs = smem_bf + 128 * SIM_TILE_STRIDE;
    float* red_c = (float*)(smem_bf + 2 * 128 * SIM_TILE_STRIDE);  // [8][32]

    const int tid  = threadIdx.x;
    const int wid  = tid >> 5, lane = tid & 31;
    const int g    = lane >> 2, tq = lane & 3;
    const int wr   = (wid >> 2) * 64;
    const int wn   = wid & 3;
    const int wc   = wn * 32;
    const int row0 = bi * 128;

    // Load A tile once
    {
        const uint4* src = (const uint4*)(g_zh + row0 * D_OUT);
        uint4* dst = (uint4*)As;
        for (int idx = tid; idx < 2048; idx += 256) {
            int r = idx >> 4, c = idx & 15;
            dst[r * 17 + c] = src[idx];
        }
    }

    float rowAcc[4][2] = {};

    for (int bj = bj0; bj < jend; bj++) {
        const int col0 = bj * 128;
        const bool diag = (bj == bi);
        __syncthreads();   // Bs + red_c free
        {
            const uint4* src = (const uint4*)(g_zh + col0 * D_OUT);
            uint4* dst = (uint4*)Bs;
            for (int idx = tid; idx < 2048; idx += 256) {
                int r = idx >> 4, c = idx & 15;
                dst[r * 17 + c] = src[idx];
            }
        }
        __syncthreads();

        float acc[4][4][4] = {};
        #pragma unroll
        for (int kk = 0; kk < 128; kk += 16) {
            uint32_t a[4][4], b[4][2];
            #pragma unroll
            for (int mi = 0; mi < 4; mi++) {
                const __nv_bfloat16* ap = As + (wr + mi * 16 + g) * SIM_TILE_STRIDE + kk + tq * 2;
                a[mi][0] = *(const uint32_t*)ap;
                a[mi][1] = *(const uint32_t*)(ap + 8 * SIM_TILE_STRIDE);
                a[mi][2] = *(const uint32_t*)(ap + 8);
                a[mi][3] = *(const uint32_t*)(ap + 8 * SIM_TILE_STRIDE + 8);
            }
            #pragma unroll
            for (int ni = 0; ni < 4; ni++) {
                const __nv_bfloat16* bp = Bs + (wc + ni * 8 + g) * SIM_TILE_STRIDE + kk + tq * 2;
                b[ni][0] = *(const uint32_t*)bp;
                b[ni][1] = *(const uint32_t*)(bp + 8);
            }
            #pragma unroll
            for (int mi = 0; mi < 4; mi++)
                #pragma unroll
                for (int ni = 0; ni < 4; ni++)
                    mma_bf16(acc[mi][ni], a[mi], b[ni]);
        }

        // Epilogue: exp(2*sim); zero diagonal on diag tile; row + col partials
        float colAcc[4][2] = {};
        #pragma unroll
        for (int mi = 0; mi < 4; mi++) {
            const int lr0 = wr + mi * 16 + g;
            const int lr1 = lr0 + 8;
            #pragma unroll
            for (int ni = 0; ni < 4; ni++) {
                const int lj0 = wc + ni * 8 + tq * 2;
                float e00 = __expf(2.0f * acc[mi][ni][0]);
                float e01 = __expf(2.0f * acc[mi][ni][1]);
                float e10 = __expf(2.0f * acc[mi][ni][2]);
                float e11 = __expf(2.0f * acc[mi][ni][3]);
                if (diag) {
                    if (lj0     == lr0) e00 = 0.f;
                    if (lj0 + 1 == lr0) e01 = 0.f;
                    if (lj0     == lr1) e10 = 0.f;
                    if (lj0 + 1 == lr1) e11 = 0.f;
                }
                rowAcc[mi][0] += e00 + e01;
                rowAcc[mi][1] += e10 + e11;
                colAcc[ni][0] += e00 + e10;
                colAcc[ni][1] += e01 + e11;
            }
        }

        // col reduce over g lanes (XOR 4,8,16); stage to red_c; write
        #pragma unroll
        for (int ni = 0; ni < 4; ni++)
            #pragma unroll
            for (int h = 0; h < 2; h++) {
                float s = colAcc[ni][h];
                s += __shfl_xor_sync(0xffffffffu, s, 4);
                s += __shfl_xor_sync(0xffffffffu, s, 8);
                s += __shfl_xor_sync(0xffffffffu, s, 16);
                colAcc[ni][h] = s;
            }
        if (g == 0) {
            #pragma unroll
            for (int ni = 0; ni < 4; ni++) {
                red_c[wid * 32 + ni * 8 + tq * 2]     = colAcc[ni][0];
                red_c[wid * 32 + ni * 8 + tq * 2 + 1] = colAcc[ni][1];
            }
        }
        __syncthreads();
        if (tid < 128) {
            int wgrp = tid >> 5, jl = tid & 31;
            float cs = diag ? 0.f : (red_c[wgrp * 32 + jl] + red_c[(wgrp + 4) * 32 + jl]);
            g_partial_c[bi * N2 + col0 + tid] = cs;
        }
    }

    // Row reduce: over tq lanes, then across wn warp groups via smem (reuse As)
    #pragma unroll
    for (int mi = 0; mi < 4; mi++)
        #pragma unroll
        for (int h = 0; h < 2; h++) {
            float s = rowAcc[mi][h];
            s += __shfl_xor_sync(0xffffffffu, s, 1);
            s += __shfl_xor_sync(0xffffffffu, s, 2);
            rowAcc[mi][h] = s;
        }
    __syncthreads();                      // done with As/Bs
    float* red_r = (float*)smem_bf;       // [4 wn][128 rows]
    if (tq == 0) {
        #pragma unroll
        for (int mi = 0; mi < 4; mi++) {
            red_r[wn * 128 + wr + mi * 16 + g]     = rowAcc[mi][0];
            red_r[wn * 128 + wr + mi * 16 + g + 8] = rowAcc[mi][1];
        }
    }
    __syncthreads();
    if (tid < 128) {
        float rs = red_r[tid] + red_r[128 + tid] + red_r[256 + tid] + red_r[384 + tid];
        g_partial_r[rem * N2 + row0 + tid] = rs;
    }
}

// ============================================================================
// rowloss[i] = log(sum of written partials) - pos[i]
// Row block b: r[t][i] for t < ceil((64-b)/4);  c[x][i] for x in [0,b].
// ============================================================================
__global__ void rowloss_kernel()
{
    const int i = blockIdx.x * 128 + threadIdx.x;
    const int b = i >> 7;
    const int ng = (64 - b + 3) >> 2;
    float se = 0.f;
    for (int t = 0; t < ng; t++) se += g_partial_r[t * N2 + i];
    for (int x = 0; x <= b; x++) se += g_partial_c[x * N2 + i];
    g_rowloss[i] = logf(se) - g_pos[i];
}

// ============================================================================
// loss = mean(rowloss)
// ============================================================================
__global__ void loss_kernel(float* __restrict__ out)
{
    __shared__ float sh[256];
    float s = 0.f;
    for (int i = threadIdx.x; i < N2; i += 256) s += g_rowloss[i];
    sh[threadIdx.x] = s;
    __syncthreads();
    for (int o = 128; o; o >>= 1) {
        if (threadIdx.x < o) sh[threadIdx.x] += sh[threadIdx.x + o];
        __syncthreads();
    }
    if (threadIdx.x == 0) out[0] = sh[0] * (1.0f / N2);
}

// ============================================================================
extern "C" void kernel_launch(void* const* d_in, const int* in_sizes, int n_in,
                              void* d_out, int out_size)
{
    const float* h1    = (const float*)d_in[0];
    const float* h2    = (const float*)d_in[1];
    const float* W1    = (const float*)d_in[2];
    const float* b1    = (const float*)d_in[3];
    const float* gamma = (const float*)d_in[4];
    const float* beta  = (const float*)d_in[5];
    const float* W2    = (const float*)d_in[6];
    const float* b2    = (const float*)d_in[7];
    float* out = (float*)d_out;

    cudaFuncSetAttribute(sim_kernel, cudaFuncAttributeMaxDynamicSharedMemorySize,
                         SIM_SMEM_BYTES);

    gemm1_kernel<<<dim3(N2 / 128, D_HID / 64), 256>>>(h1, h2, W1, b1);
    bn_stats_kernel<<<dim3(D_HID / 64, 2), dim3(64, 4)>>>(gamma, beta);
    gemm2_kernel<<<dim3(N2 / 128, D_OUT / 64), 256>>>(W2, b2);
    norm_kernel<<<N2 / 8, 256>>>(out);
    pos_kernel<<<BATCH / 8, 256>>>();
    sim_kernel<<<SIM_GROUPS, 256, SIM_SMEM_BYTES>>>();
    rowloss_kernel<<<N2 / 128, 128>>>();
    loss_kernel<<<1, 256>>>(out);
}

// round 7
// speedup vs baseline: 2.1509x; 1.4500x over previous
#include <cuda_runtime.h>
#include <cuda_bf16.h>
#include <math.h>
#include <stdint.h>

// Problem dims
#define BATCH   4096
#define D_IN    192
#define D_HID   512
#define D_OUT   128
#define N2      8192            // 2*BATCH
#define TEMP_INV 2.0f           // 1/0.5
#define BN_EPS   1e-5f

// Sim symmetric-tiling config
#define SIM_GROUPS 544          // sum_{bi} ceil((64-bi)/4)
#define SIM_MAX_T  16

// ---------------- scratch (device globals; no allocation allowed) ----------
__device__ float g_y[N2 * D_HID];          // 16 MB
__device__ float g_bn_ps[32 * 1024];       // per-slice column sums
__device__ float g_bn_pq[32 * 1024];       // per-slice column sumsq
__device__ float g_bn_scale[2 * D_HID];
__device__ float g_bn_bias[2 * D_HID];
__device__ float g_zraw[N2 * D_OUT];
__device__ float g_z[N2 * D_OUT];
__device__ __nv_bfloat16 g_zh[N2 * D_OUT];
__device__ float g_partial_r[SIM_MAX_T * N2];
__device__ float g_partial_c[64 * N2];
__device__ float g_rowloss[N2];
__device__ float g_pos[N2];

// ============================================================================
// helpers
// ============================================================================
__device__ __forceinline__ float to_tf32(float x) {
    float r;
    asm("cvt.rna.tf32.f32 %0, %1;" : "=f"(r) : "f"(x));
    return r;
}
__device__ __forceinline__ void mma_tf32(float* c, const uint32_t* a, const uint32_t* b)
{
    asm volatile(
        "mma.sync.aligned.m16n8k8.row.col.f32.tf32.tf32.f32 "
        "{%0,%1,%2,%3}, {%4,%5,%6,%7}, {%8,%9}, {%0,%1,%2,%3};"
        : "+f"(c[0]), "+f"(c[1]), "+f"(c[2]), "+f"(c[3])
        : "r"(a[0]), "r"(a[1]), "r"(a[2]), "r"(a[3]), "r"(b[0]), "r"(b[1]));
}
__device__ __forceinline__ void mma_bf16(float* c, const uint32_t* a, const uint32_t* b)
{
    asm volatile(
        "mma.sync.aligned.m16n8k16.row.col.f32.bf16.bf16.f32 "
        "{%0,%1,%2,%3}, {%4,%5,%6,%7}, {%8,%9}, {%0,%1,%2,%3};"
        : "+f"(c[0]), "+f"(c[1]), "+f"(c[2]), "+f"(c[3])
        : "r"(a[0]), "r"(a[1]), "r"(a[2]), "r"(a[3]), "r"(b[0]), "r"(b[1]));
}
__device__ __forceinline__ uint32_t smem_u32(const void* p) {
    uint32_t a;
    asm("{ .reg .u64 t; cvta.to.shared.u64 t, %1; cvt.u32.u64 %0, t; }" : "=r"(a) : "l"(p));
    return a;
}
#define CP_ASYNC16(dst, src) \
    asm volatile("cp.async.cg.shared.global [%0], [%1], 16;" :: "r"(dst), "l"(src))
#define CP_COMMIT()  asm volatile("cp.async.commit_group;" ::: "memory")
#define CP_WAIT0()   asm volatile("cp.async.wait_group 0;" ::: "memory")
#define CP_WAIT1()   asm volatile("cp.async.wait_group 1;" ::: "memory")

// ============================================================================
// GEMM1 (tf32): y = X @ W1^T + b1.  M=8192, N=512, K=192. Tile 128x64.
// ============================================================================
#define G1_AS 36
__global__ __launch_bounds__(256) void gemm1_kernel(
    const float* __restrict__ h1, const float* __restrict__ h2,
    const float* __restrict__ W1, const float* __restrict__ b1)
{
    __shared__ float As[128][G1_AS];
    __shared__ float Bs[64][G1_AS];
    const int tid  = threadIdx.x;
    const int wid  = tid >> 5, lane = tid & 31;
    const int g    = lane >> 2, tq = lane & 3;
    const int wr   = (wid >> 1) * 32;
    const int wc   = (wid & 1) * 32;
    const int row0 = blockIdx.x * 128;
    const int col0 = blockIdx.y * 64;
    const float* A = (row0 < BATCH) ? h1 : h2;
    const int arow0 = (row0 < BATCH) ? row0 : (row0 - BATCH);

    float acc[2][4][4] = {};

    for (int kt = 0; kt < D_IN; kt += 32) {
        const int kt4 = kt >> 2;
        #pragma unroll
        for (int it = 0; it < 4; it++) {
            int idx = tid + it * 256;
            int r = idx >> 3, c = idx & 7;
            float4 v = ((const float4*)A)[(arow0 + r) * 48 + kt4 + c];
            float* d = &As[r][c * 4];
            d[0] = to_tf32(v.x); d[1] = to_tf32(v.y);
            d[2] = to_tf32(v.z); d[3] = to_tf32(v.w);
        }
        #pragma unroll
        for (int it = 0; it < 2; it++) {
            int idx = tid + it * 256;
            int r = idx >> 3, c = idx & 7;
            float4 v = ((const float4*)W1)[(col0 + r) * 48 + kt4 + c];
            float* d = &Bs[r][c * 4];
            d[0] = to_tf32(v.x); d[1] = to_tf32(v.y);
            d[2] = to_tf32(v.z); d[3] = to_tf32(v.w);
        }
        __syncthreads();
        #pragma unroll
        for (int kk = 0; kk < 4; kk++) {
            uint32_t a[2][4], b[4][2];
            #pragma unroll
            for (int mi = 0; mi < 2; mi++) {
                const uint32_t* ap = (const uint32_t*)&As[wr + mi * 16 + g][kk * 8 + tq];
                a[mi][0] = ap[0];
                a[mi][1] = ap[8 * G1_AS];
                a[mi][2] = ap[4];
                a[mi][3] = ap[8 * G1_AS + 4];
            }
            #pragma unroll
            for (int ni = 0; ni < 4; ni++) {
                const uint32_t* bp = (const uint32_t*)&Bs[wc + ni * 8 + g][kk * 8 + tq];
                b[ni][0] = bp[0];
                b[ni][1] = bp[4];
            }
            #pragma unroll
            for (int mi = 0; mi < 2; mi++)
                #pragma unroll
                for (int ni = 0; ni < 4; ni++)
                    mma_tf32(acc[mi][ni], a[mi], b[ni]);
        }
        __syncthreads();
    }
    #pragma unroll
    for (int mi = 0; mi < 2; mi++) {
        const int r0 = row0 + wr + mi * 16 + g;
        #pragma unroll
        for (int ni = 0; ni < 4; ni++) {
            const int c0 = col0 + wc + ni * 8 + tq * 2;
            g_y[r0 * D_HID + c0]           = acc[mi][ni][0] + b1[c0];
            g_y[r0 * D_HID + c0 + 1]       = acc[mi][ni][1] + b1[c0 + 1];
            g_y[(r0 + 8) * D_HID + c0]     = acc[mi][ni][2] + b1[c0];
            g_y[(r0 + 8) * D_HID + c0 + 1] = acc[mi][ni][3] + b1[c0 + 1];
        }
    }
}

// ============================================================================
// BN stage 1: per-slice (128 rows) column sums. grid (4, 32), block 256.
// c = combined col in [0,1024): head = c>>9, col = c&511.
// ============================================================================
__global__ void bn_part_kernel()
{
    const int c    = blockIdx.x * 256 + threadIdx.x;
    const int head = c >> 9;
    const int col  = c & 511;
    const int r0   = blockIdx.y * 128;
    const float* Y = g_y + (head * BATCH + r0) * D_HID + col;
    float s = 0.f, sq = 0.f;
    #pragma unroll 8
    for (int r = 0; r < 128; r++) {
        float v = Y[r * D_HID];
        s += v; sq += v * v;
    }
    g_bn_ps[blockIdx.y * 1024 + c] = s;
    g_bn_pq[blockIdx.y * 1024 + c] = sq;
}

// BN stage 2: finalize scale/bias. grid 4, block 256.
__global__ void bn_final_kernel(const float* __restrict__ gamma,
                                const float* __restrict__ beta)
{
    const int c   = blockIdx.x * 256 + threadIdx.x;
    const int col = c & 511;
    float s = 0.f, sq = 0.f;
    #pragma unroll
    for (int k = 0; k < 32; k++) {
        s  += g_bn_ps[k * 1024 + c];
        sq += g_bn_pq[k * 1024 + c];
    }
    float mean = s * (1.0f / BATCH);
    float var  = sq * (1.0f / BATCH) - mean * mean;
    float a = gamma[col] * rsqrtf(var + BN_EPS);
    g_bn_scale[c] = a;
    g_bn_bias[c]  = beta[col] - mean * a;
}

// ============================================================================
// GEMM2 (tf32): zraw = relu(bn(y)) @ W2^T + b2.  Tile 64x128, grid 128.
// g_y read exactly once; W2 (256 KB) L2-resident.
// ============================================================================
__global__ __launch_bounds__(256) void gemm2_kernel(
    const float* __restrict__ W2, const float* __restrict__ b2)
{
    __shared__ float As[64][G1_AS];
    __shared__ float Bs[128][G1_AS];
    const int tid  = threadIdx.x;
    const int wid  = tid >> 5, lane = tid & 31;
    const int g    = lane >> 2, tq = lane & 3;
    const int wr   = (wid >> 2) * 32;      // 2 warp-rows
    const int wc   = (wid & 3) * 32;       // 4 warp-cols
    const int row0 = blockIdx.x * 64;
    const int head = row0 >> 12;
    const float* sc = g_bn_scale + head * D_HID;
    const float* bi = g_bn_bias  + head * D_HID;

    float acc[2][4][4] = {};

    for (int kt = 0; kt < D_HID; kt += 32) {
        const int kt4 = kt >> 2;
        // As: 64 rows x 8 float4 = 512 entries
        #pragma unroll
        for (int it = 0; it < 2; it++) {
            int idx = tid + it * 256;
            int r = idx >> 3, c = idx & 7;
            float4 v = ((const float4*)g_y)[(row0 + r) * 128 + kt4 + c];
            float4 s4 = ((const float4*)sc)[kt4 + c];
            float4 o4 = ((const float4*)bi)[kt4 + c];
            float* d = &As[r][c * 4];
            d[0] = to_tf32(fmaxf(fmaf(v.x, s4.x, o4.x), 0.f));
            d[1] = to_tf32(fmaxf(fmaf(v.y, s4.y, o4.y), 0.f));
            d[2] = to_tf32(fmaxf(fmaf(v.z, s4.z, o4.z), 0.f));
            d[3] = to_tf32(fmaxf(fmaf(v.w, s4.w, o4.w), 0.f));
        }
        // Bs: 128 rows x 8 float4 = 1024 entries
        #pragma unroll
        for (int it = 0; it < 4; it++) {
            int idx = tid + it * 256;
            int r = idx >> 3, c = idx & 7;
            float4 v = ((const float4*)W2)[r * 128 + kt4 + c];
            float* d = &Bs[r][c * 4];
            d[0] = to_tf32(v.x); d[1] = to_tf32(v.y);
            d[2] = to_tf32(v.z); d[3] = to_tf32(v.w);
        }
        __syncthreads();
        #pragma unroll
        for (int kk = 0; kk < 4; kk++) {
            uint32_t a[2][4], b[4][2];
            #pragma unroll
            for (int mi = 0; mi < 2; mi++) {
                const uint32_t* ap = (const uint32_t*)&As[wr + mi * 16 + g][kk * 8 + tq];
                a[mi][0] = ap[0];
                a[mi][1] = ap[8 * G1_AS];
                a[mi][2] = ap[4];
                a[mi][3] = ap[8 * G1_AS + 4];
            }
            #pragma unroll
            for (int ni = 0; ni < 4; ni++) {
                const uint32_t* bp = (const uint32_t*)&Bs[wc + ni * 8 + g][kk * 8 + tq];
                b[ni][0] = bp[0];
                b[ni][1] = bp[4];
            }
            #pragma unroll
            for (int mi = 0; mi < 2; mi++)
                #pragma unroll
                for (int ni = 0; ni < 4; ni++)
                    mma_tf32(acc[mi][ni], a[mi], b[ni]);
        }
        __syncthreads();
    }
    #pragma unroll
    for (int mi = 0; mi < 2; mi++) {
        const int r0 = row0 + wr + mi * 16 + g;
        #pragma unroll
        for (int ni = 0; ni < 4; ni++) {
            const int c0 = wc + ni * 8 + tq * 2;
            g_zraw[r0 * D_OUT + c0]           = acc[mi][ni][0] + b2[c0];
            g_zraw[r0 * D_OUT + c0 + 1]       = acc[mi][ni][1] + b2[c0 + 1];
            g_zraw[(r0 + 8) * D_OUT + c0]     = acc[mi][ni][2] + b2[c0];
            g_zraw[(r0 + 8) * D_OUT + c0 + 1] = acc[mi][ni][3] + b2[c0 + 1];
        }
    }
}

// ============================================================================
// norm + pos fused. Block 256 = 8 warps: warps 0-3 rows pi, warps 4-7 rows
// pi+BATCH (partner). After normalize, partners exchange via smem for pos.
// Grid 1024 (4 pairs per block).
// ============================================================================
__global__ void norm_kernel(float* __restrict__ out)
{
    const int tid  = threadIdx.x;
    const int wid  = tid >> 5, lane = tid & 31;
    const int pi   = blockIdx.x * 4 + (wid & 3);      // pair index
    const int row  = (wid < 4) ? pi : pi + BATCH;

    const float4 v = ((const float4*)(g_zraw + row * D_OUT))[lane];
    float s = v.x * v.x + v.y * v.y + v.z * v.z + v.w * v.w;
    #pragma unroll
    for (int o = 16; o; o >>= 1) s += __shfl_xor_sync(0xffffffffu, s, o);
    const float inv = 1.0f / fmaxf(sqrtf(s), 1e-12f);
    float4 z = make_float4(v.x * inv, v.y * inv, v.z * inv, v.w * inv);
    ((float4*)(g_z + row * D_OUT))[lane] = z;
    __nv_bfloat162* zh2 = (__nv_bfloat162*)(g_zh + row * D_OUT);
    zh2[lane * 2 + 0] = __nv_bfloat162(__float2bfloat16(z.x), __float2bfloat16(z.y));
    zh2[lane * 2 + 1] = __nv_bfloat162(__float2bfloat16(z.z), __float2bfloat16(z.w));
    float* o4 = out + 1 + row * D_OUT + lane * 4;
    o4[0] = z.x; o4[1] = z.y; o4[2] = z.z; o4[3] = z.w;

    __shared__ float4 zsh[4][32];
    if (wid >= 4) zsh[wid - 4][lane] = z;
    __syncthreads();
    if (wid < 4) {
        float4 p = zsh[wid][lane];
        float d = z.x * p.x + z.y * p.y + z.z * p.z + z.w * p.w;
        #pragma unroll
        for (int o = 16; o; o >>= 1) d += __shfl_xor_sync(0xffffffffu, d, o);
        if (lane == 0) {
            float pv = d * TEMP_INV;
            g_pos[pi] = pv;
            g_pos[pi + BATCH] = pv;
        }
    }
}

// ============================================================================
// Symmetric sim, grouped, with cp.async double-buffered B tiles.
// Block = (row panel bi) x (group of <=4 col tiles). 544 blocks, 2/SM.
// ============================================================================
#define SIM_TILE_STRIDE 136
#define SIM_TILE_BYTES  (128 * SIM_TILE_STRIDE * 2)              // 34816
#define SIM_SMEM_BYTES  (3 * SIM_TILE_BYTES + 1024)              // 105472

__global__ __launch_bounds__(256, 2) void sim_kernel()
{
    // Map 1-D block id -> (bi, group)
    int rem = blockIdx.x, bi = 0;
    for (;;) {
        int cnt = (64 - bi + 3) >> 2;
        if (rem < cnt) break;
        rem -= cnt; bi++;
    }
    const int bj0  = bi + rem * 4;
    const int jend = (bj0 + 4 < 64) ? bj0 + 4 : 64;

    extern __shared__ __nv_bfloat16 smem_bf[];
    __nv_bfloat16* As  = smem_bf;
    __nv_bfloat16* Bs0 = smem_bf + 128 * SIM_TILE_STRIDE;
    __nv_bfloat16* Bs1 = Bs0 + 128 * SIM_TILE_STRIDE;
    float* red_c = (float*)(Bs1 + 128 * SIM_TILE_STRIDE);   // [8][32]
    const uint32_t bs0_u = smem_u32(Bs0);
    const uint32_t bs1_u = smem_u32(Bs1);

    const int tid  = threadIdx.x;
    const int wid  = tid >> 5, lane = tid & 31;
    const int g    = lane >> 2, tq = lane & 3;
    const int wr   = (wid >> 2) * 64;
    const int wn   = wid & 3;
    const int wc   = wn * 32;
    const int row0 = bi * 128;

    // Prefetch first B tile
    {
        const char* src = (const char*)(g_zh + bj0 * 128 * D_OUT);
        for (int idx = tid; idx < 2048; idx += 256) {
            int r = idx >> 4, c = idx & 15;
            CP_ASYNC16(bs0_u + (uint32_t)(r * 17 + c) * 16, src + idx * 16);
        }
        CP_COMMIT();
    }

    // Load A tile (regular loads; overlaps with prefetch)
    {
        const uint4* src = (const uint4*)(g_zh + row0 * D_OUT);
        uint4* dst = (uint4*)As;
        for (int idx = tid; idx < 2048; idx += 256) {
            int r = idx >> 4, c = idx & 15;
            dst[r * 17 + c] = src[idx];
        }
    }

    float rowAcc[4][2] = {};
    int buf = 0;

    for (int bj = bj0; bj < jend; bj++) {
        const bool diag = (bj == bi);
        const bool has_next = (bj + 1 < jend);
        // Prefetch next B into other buffer
        if (has_next) {
            const char* src = (const char*)(g_zh + (bj + 1) * 128 * D_OUT);
            uint32_t dst_u = buf ? bs0_u : bs1_u;
            for (int idx = tid; idx < 2048; idx += 256) {
                int r = idx >> 4, c = idx & 15;
                CP_ASYNC16(dst_u + (uint32_t)(r * 17 + c) * 16, src + idx * 16);
            }
            CP_COMMIT();
            CP_WAIT1();       // current tile landed; next still in flight
        } else {
            CP_WAIT0();
        }
        __syncthreads();

        const __nv_bfloat16* Bs = buf ? Bs1 : Bs0;

        float acc[4][4][4] = {};
        #pragma unroll
        for (int kk = 0; kk < 128; kk += 16) {
            uint32_t a[4][4], b[4][2];
            #pragma unroll
            for (int mi = 0; mi < 4; mi++) {
                const __nv_bfloat16* ap = As + (wr + mi * 16 + g) * SIM_TILE_STRIDE + kk + tq * 2;
                a[mi][0] = *(const uint32_t*)ap;
                a[mi][1] = *(const uint32_t*)(ap + 8 * SIM_TILE_STRIDE);
                a[mi][2] = *(const uint32_t*)(ap + 8);
                a[mi][3] = *(const uint32_t*)(ap + 8 * SIM_TILE_STRIDE + 8);
            }
            #pragma unroll
            for (int ni = 0; ni < 4; ni++) {
                const __nv_bfloat16* bp = Bs + (wc + ni * 8 + g) * SIM_TILE_STRIDE + kk + tq * 2;
                b[ni][0] = *(const uint32_t*)bp;
                b[ni][1] = *(const uint32_t*)(bp + 8);
            }
            #pragma unroll
            for (int mi = 0; mi < 4; mi++)
                #pragma unroll
                for (int ni = 0; ni < 4; ni++)
                    mma_bf16(acc[mi][ni], a[mi], b[ni]);
        }

        // Epilogue
        float colAcc[4][2] = {};
        #pragma unroll
        for (int mi = 0; mi < 4; mi++) {
            const int lr0 = wr + mi * 16 + g;
            const int lr1 = lr0 + 8;
            #pragma unroll
            for (int ni = 0; ni < 4; ni++) {
                const int lj0 = wc + ni * 8 + tq * 2;
                float e00 = __expf(2.0f * acc[mi][ni][0]);
                float e01 = __expf(2.0f * acc[mi][ni][1]);
                float e10 = __expf(2.0f * acc[mi][ni][2]);
                float e11 = __expf(2.0f * acc[mi][ni][3]);
                if (diag) {
                    if (lj0     == lr0) e00 = 0.f;
                    if (lj0 + 1 == lr0) e01 = 0.f;
                    if (lj0     == lr1) e10 = 0.f;
                    if (lj0 + 1 == lr1) e11 = 0.f;
                }
                rowAcc[mi][0] += e00 + e01;
                rowAcc[mi][1] += e10 + e11;
                colAcc[ni][0] += e00 + e10;
                colAcc[ni][1] += e01 + e11;
            }
        }

        #pragma unroll
        for (int ni = 0; ni < 4; ni++)
            #pragma unroll
            for (int h = 0; h < 2; h++) {
                float s = colAcc[ni][h];
                s += __shfl_xor_sync(0xffffffffu, s, 4);
                s += __shfl_xor_sync(0xffffffffu, s, 8);
                s += __shfl_xor_sync(0xffffffffu, s, 16);
                colAcc[ni][h] = s;
            }
        if (g == 0) {
            #pragma unroll
            for (int ni = 0; ni < 4; ni++) {
                red_c[wid * 32 + ni * 8 + tq * 2]     = colAcc[ni][0];
                red_c[wid * 32 + ni * 8 + tq * 2 + 1] = colAcc[ni][1];
            }
        }
        __syncthreads();
        if (tid < 128) {
            int wgrp = tid >> 5, jl = tid & 31;
            float cs = diag ? 0.f : (red_c[wgrp * 32 + jl] + red_c[(wgrp + 4) * 32 + jl]);
            g_partial_c[bi * N2 + bj * 128 + tid] = cs;
        }
        buf ^= 1;
    }

    // Row reduce
    #pragma unroll
    for (int mi = 0; mi < 4; mi++)
        #pragma unroll
        for (int h = 0; h < 2; h++) {
            float s = rowAcc[mi][h];
            s += __shfl_xor_sync(0xffffffffu, s, 1);
            s += __shfl_xor_sync(0xffffffffu, s, 2);
            rowAcc[mi][h] = s;
        }
    __syncthreads();
    float* red_r = (float*)smem_bf;
    if (tq == 0) {
        #pragma unroll
        for (int mi = 0; mi < 4; mi++) {
            red_r[wn * 128 + wr + mi * 16 + g]     = rowAcc[mi][0];
            red_r[wn * 128 + wr + mi * 16 + g + 8] = rowAcc[mi][1];
        }
    }
    __syncthreads();
    if (tid < 128) {
        float rs = red_r[tid] + red_r[128 + tid] + red_r[256 + tid] + red_r[384 + tid];
        g_partial_r[rem * N2 + row0 + tid] = rs;
    }
}

// ============================================================================
// rowloss[i] = log(sum of written partials) - pos[i]
// ============================================================================
__global__ void rowloss_kernel()
{
    const int i = blockIdx.x * 128 + threadIdx.x;
    const int b = i >> 7;
    const int ng = (64 - b + 3) >> 2;
    float se = 0.f;
    for (int t = 0; t < ng; t++) se += g_partial_r[t * N2 + i];
    for (int x = 0; x <= b; x++) se += g_partial_c[x * N2 + i];
    g_rowloss[i] = logf(se) - g_pos[i];
}

// ============================================================================
// loss = mean(rowloss)
// ============================================================================
__global__ void loss_kernel(float* __restrict__ out)
{
    __shared__ float sh[256];
    float s = 0.f;
    for (int i = threadIdx.x; i < N2; i += 256) s += g_rowloss[i];
    sh[threadIdx.x] = s;
    __syncthreads();
    for (int o = 128; o; o >>= 1) {
        if (threadIdx.x < o) sh[threadIdx.x] += sh[threadIdx.x + o];
        __syncthreads();
    }
    if (threadIdx.x == 0) out[0] = sh[0] * (1.0f / N2);
}

// ============================================================================
extern "C" void kernel_launch(void* const* d_in, const int* in_sizes, int n_in,
                              void* d_out, int out_size)
{
    const float* h1    = (const float*)d_in[0];
    const float* h2    = (const float*)d_in[1];
    const float* W1    = (const float*)d_in[2];
    const float* b1    = (const float*)d_in[3];
    const float* gamma = (const float*)d_in[4];
    const float* beta  = (const float*)d_in[5];
    const float* W2    = (const float*)d_in[6];
    const float* b2    = (const float*)d_in[7];
    float* out = (float*)d_out;

    cudaFuncSetAttribute(sim_kernel, cudaFuncAttributeMaxDynamicSharedMemorySize,
                         SIM_SMEM_BYTES);

    gemm1_kernel<<<dim3(N2 / 128, D_HID / 64), 256>>>(h1, h2, W1, b1);
    bn_part_kernel<<<dim3(4, 32), 256>>>();
    bn_final_kernel<<<4, 256>>>(gamma, beta);
    gemm2_kernel<<<N2 / 64, 256>>>(W2, b2);
    norm_kernel<<<BATCH / 4, 256>>>(out);
    sim_kernel<<<SIM_GROUPS, 256, SIM_SMEM_BYTES>>>();
    rowloss_kernel<<<N2 / 128, 128>>>();
    loss_kernel<<<1, 256>>>(out);
}

// round 8
// speedup vs baseline: 2.3184x; 1.0779x over previous
#include <cuda_runtime.h>
#include <cuda_bf16.h>
#include <math.h>
#include <stdint.h>

// Problem dims
#define BATCH   4096
#define D_IN    192
#define D_HID   512
#define D_OUT   128
#define N2      8192            // 2*BATCH
#define TEMP_INV 2.0f           // 1/0.5
#define BN_EPS   1e-5f

// Sim symmetric-tiling config
#define SIM_GROUPS 544          // sum_{bi} ceil((64-bi)/4)
#define SIM_MAX_T  16

// ---------------- scratch (device globals; no allocation allowed) ----------
__device__ float g_y[N2 * D_HID];          // 16 MB
__device__ float g_bn_ps[32 * 1024];
__device__ float g_bn_pq[32 * 1024];
__device__ float g_bn_scale[2 * D_HID];
__device__ float g_bn_bias[2 * D_HID];
__device__ float g_zp0[N2 * D_OUT];        // gemm2 split-K partial 0
__device__ float g_zp1[N2 * D_OUT];        // gemm2 split-K partial 1
__device__ float g_z[N2 * D_OUT];
__device__ __nv_bfloat16 g_zh[N2 * D_OUT];
__device__ float g_partial_r[SIM_MAX_T * N2];
__device__ float g_partial_c[64 * N2];
__device__ float g_rowloss[N2];
__device__ float g_pos[N2];

// ============================================================================
// helpers
// ============================================================================
__device__ __forceinline__ float to_tf32(float x) {
    float r;
    asm("cvt.rna.tf32.f32 %0, %1;" : "=f"(r) : "f"(x));
    return r;
}
__device__ __forceinline__ void mma_tf32(float* c, const uint32_t* a, const uint32_t* b)
{
    asm volatile(
        "mma.sync.aligned.m16n8k8.row.col.f32.tf32.tf32.f32 "
        "{%0,%1,%2,%3}, {%4,%5,%6,%7}, {%8,%9}, {%0,%1,%2,%3};"
        : "+f"(c[0]), "+f"(c[1]), "+f"(c[2]), "+f"(c[3])
        : "r"(a[0]), "r"(a[1]), "r"(a[2]), "r"(a[3]), "r"(b[0]), "r"(b[1]));
}
__device__ __forceinline__ void mma_bf16(float* c, const uint32_t* a, const uint32_t* b)
{
    asm volatile(
        "mma.sync.aligned.m16n8k16.row.col.f32.bf16.bf16.f32 "
        "{%0,%1,%2,%3}, {%4,%5,%6,%7}, {%8,%9}, {%0,%1,%2,%3};"
        : "+f"(c[0]), "+f"(c[1]), "+f"(c[2]), "+f"(c[3])
        : "r"(a[0]), "r"(a[1]), "r"(a[2]), "r"(a[3]), "r"(b[0]), "r"(b[1]));
}
__device__ __forceinline__ uint32_t smem_u32(const void* p) {
    uint32_t a;
    asm("{ .reg .u64 t; cvta.to.shared.u64 t, %1; cvt.u32.u64 %0, t; }" : "=r"(a) : "l"(p));
    return a;
}
#define CP_ASYNC16(dst, src) \
    asm volatile("cp.async.cg.shared.global [%0], [%1], 16;" :: "r"(dst), "l"(src))
#define CP_COMMIT()  asm volatile("cp.async.commit_group;" ::: "memory")
#define CP_WAIT0()   asm volatile("cp.async.wait_group 0;" ::: "memory")
#define CP_WAIT1()   asm volatile("cp.async.wait_group 1;" ::: "memory")

// ============================================================================
// GEMM1 (tf32): y = X @ W1^T + b1.  M=8192, N=512, K=192. Tile 128x64.
// Grid (64, 8) = 512 blocks.
// ============================================================================
#define G1_AS 36
__global__ __launch_bounds__(256) void gemm1_kernel(
    const float* __restrict__ h1, const float* __restrict__ h2,
    const float* __restrict__ W1, const float* __restrict__ b1)
{
    __shared__ float As[128][G1_AS];
    __shared__ float Bs[64][G1_AS];
    const int tid  = threadIdx.x;
    const int wid  = tid >> 5, lane = tid & 31;
    const int g    = lane >> 2, tq = lane & 3;
    const int wr   = (wid >> 1) * 32;
    const int wc   = (wid & 1) * 32;
    const int row0 = blockIdx.x * 128;
    const int col0 = blockIdx.y * 64;
    const float* A = (row0 < BATCH) ? h1 : h2;
    const int arow0 = (row0 < BATCH) ? row0 : (row0 - BATCH);

    float acc[2][4][4] = {};

    for (int kt = 0; kt < D_IN; kt += 32) {
        const int kt4 = kt >> 2;
        #pragma unroll
        for (int it = 0; it < 4; it++) {
            int idx = tid + it * 256;
            int r = idx >> 3, c = idx & 7;
            float4 v = ((const float4*)A)[(arow0 + r) * 48 + kt4 + c];
            float* d = &As[r][c * 4];
            d[0] = to_tf32(v.x); d[1] = to_tf32(v.y);
            d[2] = to_tf32(v.z); d[3] = to_tf32(v.w);
        }
        #pragma unroll
        for (int it = 0; it < 2; it++) {
            int idx = tid + it * 256;
            int r = idx >> 3, c = idx & 7;
            float4 v = ((const float4*)W1)[(col0 + r) * 48 + kt4 + c];
            float* d = &Bs[r][c * 4];
            d[0] = to_tf32(v.x); d[1] = to_tf32(v.y);
            d[2] = to_tf32(v.z); d[3] = to_tf32(v.w);
        }
        __syncthreads();
        #pragma unroll
        for (int kk = 0; kk < 4; kk++) {
            uint32_t a[2][4], b[4][2];
            #pragma unroll
            for (int mi = 0; mi < 2; mi++) {
                const uint32_t* ap = (const uint32_t*)&As[wr + mi * 16 + g][kk * 8 + tq];
                a[mi][0] = ap[0];
                a[mi][1] = ap[8 * G1_AS];
                a[mi][2] = ap[4];
                a[mi][3] = ap[8 * G1_AS + 4];
            }
            #pragma unroll
            for (int ni = 0; ni < 4; ni++) {
                const uint32_t* bp = (const uint32_t*)&Bs[wc + ni * 8 + g][kk * 8 + tq];
                b[ni][0] = bp[0];
                b[ni][1] = bp[4];
            }
            #pragma unroll
            for (int mi = 0; mi < 2; mi++)
                #pragma unroll
                for (int ni = 0; ni < 4; ni++)
                    mma_tf32(acc[mi][ni], a[mi], b[ni]);
        }
        __syncthreads();
    }
    #pragma unroll
    for (int mi = 0; mi < 2; mi++) {
        const int r0 = row0 + wr + mi * 16 + g;
        #pragma unroll
        for (int ni = 0; ni < 4; ni++) {
            const int c0 = col0 + wc + ni * 8 + tq * 2;
            g_y[r0 * D_HID + c0]           = acc[mi][ni][0] + b1[c0];
            g_y[r0 * D_HID + c0 + 1]       = acc[mi][ni][1] + b1[c0 + 1];
            g_y[(r0 + 8) * D_HID + c0]     = acc[mi][ni][2] + b1[c0];
            g_y[(r0 + 8) * D_HID + c0 + 1] = acc[mi][ni][3] + b1[c0 + 1];
        }
    }
}

// ============================================================================
// BN stage 1: per-slice (128 rows) column sums. grid (4, 32), block 256.
// ============================================================================
__global__ void bn_part_kernel()
{
    const int c    = blockIdx.x * 256 + threadIdx.x;
    const int head = c >> 9;
    const int col  = c & 511;
    const int r0   = blockIdx.y * 128;
    const float* Y = g_y + (head * BATCH + r0) * D_HID + col;
    float s = 0.f, sq = 0.f;
    #pragma unroll 8
    for (int r = 0; r < 128; r++) {
        float v = Y[r * D_HID];
        s += v; sq += v * v;
    }
    g_bn_ps[blockIdx.y * 1024 + c] = s;
    g_bn_pq[blockIdx.y * 1024 + c] = sq;
}

// BN stage 2: finalize scale/bias. grid 4, block 256.
__global__ void bn_final_kernel(const float* __restrict__ gamma,
                                const float* __restrict__ beta)
{
    const int c   = blockIdx.x * 256 + threadIdx.x;
    const int col = c & 511;
    float s = 0.f, sq = 0.f;
    #pragma unroll
    for (int k = 0; k < 32; k++) {
        s  += g_bn_ps[k * 1024 + c];
        sq += g_bn_pq[k * 1024 + c];
    }
    float mean = s * (1.0f / BATCH);
    float var  = sq * (1.0f / BATCH) - mean * mean;
    float a = gamma[col] * rsqrtf(var + BN_EPS);
    g_bn_scale[c] = a;
    g_bn_bias[c]  = beta[col] - mean * a;
}

// ============================================================================
// GEMM2 (tf32, split-K=2): partial = relu(bn(y)) @ W2^T over K half.
// Tile 64x128, grid (128, 2) = 256 blocks. Partials -> g_zp0 / g_zp1.
// ============================================================================
__global__ __launch_bounds__(256) void gemm2_kernel(const float* __restrict__ W2)
{
    __shared__ float As[64][G1_AS];
    __shared__ float Bs[128][G1_AS];
    const int tid  = threadIdx.x;
    const int wid  = tid >> 5, lane = tid & 31;
    const int g    = lane >> 2, tq = lane & 3;
    const int wr   = (wid >> 2) * 32;
    const int wc   = (wid & 3) * 32;
    const int row0 = blockIdx.x * 64;
    const int ks   = blockIdx.y * 256;       // K half start
    const int head = row0 >> 12;
    const float* sc = g_bn_scale + head * D_HID;
    const float* bi = g_bn_bias  + head * D_HID;
    float* outp = blockIdx.y ? g_zp1 : g_zp0;

    float acc[2][4][4] = {};

    for (int kt = ks; kt < ks + 256; kt += 32) {
        const int kt4 = kt >> 2;
        #pragma unroll
        for (int it = 0; it < 2; it++) {
            int idx = tid + it * 256;
            int r = idx >> 3, c = idx & 7;
            float4 v = ((const float4*)g_y)[(row0 + r) * 128 + kt4 + c];
            float4 s4 = ((const float4*)sc)[kt4 + c];
            float4 o4 = ((const float4*)bi)[kt4 + c];
            float* d = &As[r][c * 4];
            d[0] = to_tf32(fmaxf(fmaf(v.x, s4.x, o4.x), 0.f));
            d[1] = to_tf32(fmaxf(fmaf(v.y, s4.y, o4.y), 0.f));
            d[2] = to_tf32(fmaxf(fmaf(v.z, s4.z, o4.z), 0.f));
            d[3] = to_tf32(fmaxf(fmaf(v.w, s4.w, o4.w), 0.f));
        }
        #pragma unroll
        for (int it = 0; it < 4; it++) {
            int idx = tid + it * 256;
            int r = idx >> 3, c = idx & 7;
            float4 v = ((const float4*)W2)[r * 128 + kt4 + c];
            float* d = &Bs[r][c * 4];
            d[0] = to_tf32(v.x); d[1] = to_tf32(v.y);
            d[2] = to_tf32(v.z); d[3] = to_tf32(v.w);
        }
        __syncthreads();
        #pragma unroll
        for (int kk = 0; kk < 4; kk++) {
            uint32_t a[2][4], b[4][2];
            #pragma unroll
            for (int mi = 0; mi < 2; mi++) {
                const uint32_t* ap = (const uint32_t*)&As[wr + mi * 16 + g][kk * 8 + tq];
                a[mi][0] = ap[0];
                a[mi][1] = ap[8 * G1_AS];
                a[mi][2] = ap[4];
                a[mi][3] = ap[8 * G1_AS + 4];
            }
            #pragma unroll
            for (int ni = 0; ni < 4; ni++) {
                const uint32_t* bp = (const uint32_t*)&Bs[wc + ni * 8 + g][kk * 8 + tq];
                b[ni][0] = bp[0];
                b[ni][1] = bp[4];
            }
            #pragma unroll
            for (int mi = 0; mi < 2; mi++)
                #pragma unroll
                for (int ni = 0; ni < 4; ni++)
                    mma_tf32(acc[mi][ni], a[mi], b[ni]);
        }
        __syncthreads();
    }
    #pragma unroll
    for (int mi = 0; mi < 2; mi++) {
        const int r0 = row0 + wr + mi * 16 + g;
        #pragma unroll
        for (int ni = 0; ni < 4; ni++) {
            const int c0 = wc + ni * 8 + tq * 2;
            outp[r0 * D_OUT + c0]           = acc[mi][ni][0];
            outp[r0 * D_OUT + c0 + 1]       = acc[mi][ni][1];
            outp[(r0 + 8) * D_OUT + c0]     = acc[mi][ni][2];
            outp[(r0 + 8) * D_OUT + c0 + 1] = acc[mi][ni][3];
        }
    }
}

// ============================================================================
// norm + pos fused (sums split-K partials + bias first).
// Block 256 = 8 warps: warps 0-3 rows pi, warps 4-7 rows pi+BATCH.
// ============================================================================
__global__ void norm_kernel(const float* __restrict__ b2, float* __restrict__ out)
{
    const int tid  = threadIdx.x;
    const int wid  = tid >> 5, lane = tid & 31;
    const int pi   = blockIdx.x * 4 + (wid & 3);
    const int row  = (wid < 4) ? pi : pi + BATCH;

    const float4 p0 = ((const float4*)(g_zp0 + row * D_OUT))[lane];
    const float4 p1 = ((const float4*)(g_zp1 + row * D_OUT))[lane];
    const float4 bb = ((const float4*)b2)[lane];
    float4 v = make_float4(p0.x + p1.x + bb.x, p0.y + p1.y + bb.y,
                           p0.z + p1.z + bb.z, p0.w + p1.w + bb.w);
    float s = v.x * v.x + v.y * v.y + v.z * v.z + v.w * v.w;
    #pragma unroll
    for (int o = 16; o; o >>= 1) s += __shfl_xor_sync(0xffffffffu, s, o);
    const float inv = 1.0f / fmaxf(sqrtf(s), 1e-12f);
    float4 z = make_float4(v.x * inv, v.y * inv, v.z * inv, v.w * inv);
    ((float4*)(g_z + row * D_OUT))[lane] = z;
    __nv_bfloat162* zh2 = (__nv_bfloat162*)(g_zh + row * D_OUT);
    zh2[lane * 2 + 0] = __nv_bfloat162(__float2bfloat16(z.x), __float2bfloat16(z.y));
    zh2[lane * 2 + 1] = __nv_bfloat162(__float2bfloat16(z.z), __float2bfloat16(z.w));
    float* o4 = out + 1 + row * D_OUT + lane * 4;
    o4[0] = z.x; o4[1] = z.y; o4[2] = z.z; o4[3] = z.w;

    __shared__ float4 zsh[4][32];
    if (wid >= 4) zsh[wid - 4][lane] = z;
    __syncthreads();
    if (wid < 4) {
        float4 p = zsh[wid][lane];
        float d = z.x * p.x + z.y * p.y + z.z * p.z + z.w * p.w;
        #pragma unroll
        for (int o = 16; o; o >>= 1) d += __shfl_xor_sync(0xffffffffu, d, o);
        if (lane == 0) {
            float pv = d * TEMP_INV;
            g_pos[pi] = pv;
            g_pos[pi + BATCH] = pv;
        }
    }
}

// ============================================================================
// Symmetric sim, grouped, cp.async double-buffered B tiles. 544 blocks, 2/SM.
// ============================================================================
#define SIM_TILE_STRIDE 136
#define SIM_TILE_BYTES  (128 * SIM_TILE_STRIDE * 2)
#define SIM_SMEM_BYTES  (3 * SIM_TILE_BYTES + 1024)   // 105472

__global__ __launch_bounds__(256, 2) void sim_kernel()
{
    int rem = blockIdx.x, bi = 0;
    for (;;) {
        int cnt = (64 - bi + 3) >> 2;
        if (rem < cnt) break;
        rem -= cnt; bi++;
    }
    const int bj0  = bi + rem * 4;
    const int jend = (bj0 + 4 < 64) ? bj0 + 4 : 64;

    extern __shared__ __nv_bfloat16 smem_bf[];
    __nv_bfloat16* As  = smem_bf;
    __nv_bfloat16* Bs0 = smem_bf + 128 * SIM_TILE_STRIDE;
    __nv_bfloat16* Bs1 = Bs0 + 128 * SIM_TILE_STRIDE;
    float* red_c = (float*)(Bs1 + 128 * SIM_TILE_STRIDE);
    const uint32_t bs0_u = smem_u32(Bs0);
    const uint32_t bs1_u = smem_u32(Bs1);

    const int tid  = threadIdx.x;
    const int wid  = tid >> 5, lane = tid & 31;
    const int g    = lane >> 2, tq = lane & 3;
    const int wr   = (wid >> 2) * 64;
    const int wn   = wid & 3;
    const int wc   = wn * 32;
    const int row0 = bi * 128;

    {
        const char* src = (const char*)(g_zh + bj0 * 128 * D_OUT);
        for (int idx = tid; idx < 2048; idx += 256) {
            int r = idx >> 4, c = idx & 15;
            CP_ASYNC16(bs0_u + (uint32_t)(r * 17 + c) * 16, src + idx * 16);
        }
        CP_COMMIT();
    }
    {
        const uint4* src = (const uint4*)(g_zh + row0 * D_OUT);
        uint4* dst = (uint4*)As;
        for (int idx = tid; idx < 2048; idx += 256) {
            int r = idx >> 4, c = idx & 15;
            dst[r * 17 + c] = src[idx];
        }
    }

    float rowAcc[4][2] = {};
    int buf = 0;

    for (int bj = bj0; bj < jend; bj++) {
        const bool diag = (bj == bi);
        const bool has_next = (bj + 1 < jend);
        if (has_next) {
            const char* src = (const char*)(g_zh + (bj + 1) * 128 * D_OUT);
            uint32_t dst_u = buf ? bs0_u : bs1_u;
            for (int idx = tid; idx < 2048; idx += 256) {
                int r = idx >> 4, c = idx & 15;
                CP_ASYNC16(dst_u + (uint32_t)(r * 17 + c) * 16, src + idx * 16);
            }
            CP_COMMIT();
            CP_WAIT1();
        } else {
            CP_WAIT0();
        }
        __syncthreads();

        const __nv_bfloat16* Bs = buf ? Bs1 : Bs0;

        float acc[4][4][4] = {};
        #pragma unroll
        for (int kk = 0; kk < 128; kk += 16) {
            uint32_t a[4][4], b[4][2];
            #pragma unroll
            for (int mi = 0; mi < 4; mi++) {
                const __nv_bfloat16* ap = As + (wr + mi * 16 + g) * SIM_TILE_STRIDE + kk + tq * 2;
                a[mi][0] = *(const uint32_t*)ap;
                a[mi][1] = *(const uint32_t*)(ap + 8 * SIM_TILE_STRIDE);
                a[mi][2] = *(const uint32_t*)(ap + 8);
                a[mi][3] = *(const uint32_t*)(ap + 8 * SIM_TILE_STRIDE + 8);
            }
            #pragma unroll
            for (int ni = 0; ni < 4; ni++) {
                const __nv_bfloat16* bp = Bs + (wc + ni * 8 + g) * SIM_TILE_STRIDE + kk + tq * 2;
                b[ni][0] = *(const uint32_t*)bp;
                b[ni][1] = *(const uint32_t*)(bp + 8);
            }
            #pragma unroll
            for (int mi = 0; mi < 4; mi++)
                #pragma unroll
                for (int ni = 0; ni < 4; ni++)
                    mma_bf16(acc[mi][ni], a[mi], b[ni]);
        }

        float colAcc[4][2] = {};
        #pragma unroll
        for (int mi = 0; mi < 4; mi++) {
            const int lr0 = wr + mi * 16 + g;
            const int lr1 = lr0 + 8;
            #pragma unroll
            for (int ni = 0; ni < 4; ni++) {
                const int lj0 = wc + ni * 8 + tq * 2;
                float e00 = __expf(2.0f * acc[mi][ni][0]);
                float e01 = __expf(2.0f * acc[mi][ni][1]);
                float e10 = __expf(2.0f * acc[mi][ni][2]);
                float e11 = __expf(2.0f * acc[mi][ni][3]);
                if (diag) {
                    if (lj0     == lr0) e00 = 0.f;
                    if (lj0 + 1 == lr0) e01 = 0.f;
                    if (lj0     == lr1) e10 = 0.f;
                    if (lj0 + 1 == lr1) e11 = 0.f;
                }
                rowAcc[mi][0] += e00 + e01;
                rowAcc[mi][1] += e10 + e11;
                colAcc[ni][0] += e00 + e10;
                colAcc[ni][1] += e01 + e11;
            }
        }

        #pragma unroll
        for (int ni = 0; ni < 4; ni++)
            #pragma unroll
            for (int h = 0; h < 2; h++) {
                float s = colAcc[ni][h];
                s += __shfl_xor_sync(0xffffffffu, s, 4);
                s += __shfl_xor_sync(0xffffffffu, s, 8);
                s += __shfl_xor_sync(0xffffffffu, s, 16);
                colAcc[ni][h] = s;
            }
        if (g == 0) {
            #pragma unroll
            for (int ni = 0; ni < 4; ni++) {
                red_c[wid * 32 + ni * 8 + tq * 2]     = colAcc[ni][0];
                red_c[wid * 32 + ni * 8 + tq * 2 + 1] = colAcc[ni][1];
            }
        }
        __syncthreads();
        if (tid < 128) {
            int wgrp = tid >> 5, jl = tid & 31;
            float cs = diag ? 0.f : (red_c[wgrp * 32 + jl] + red_c[(wgrp + 4) * 32 + jl]);
            g_partial_c[bi * N2 + bj * 128 + tid] = cs;
        }
        buf ^= 1;
    }

    #pragma unroll
    for (int mi = 0; mi < 4; mi++)
        #pragma unroll
        for (int h = 0; h < 2; h++) {
            float s = rowAcc[mi][h];
            s += __shfl_xor_sync(0xffffffffu, s, 1);
            s += __shfl_xor_sync(0xffffffffu, s, 2);
            rowAcc[mi][h] = s;
        }
    __syncthreads();
    float* red_r = (float*)smem_bf;
    if (tq == 0) {
        #pragma unroll
        for (int mi = 0; mi < 4; mi++) {
            red_r[wn * 128 + wr + mi * 16 + g]     = rowAcc[mi][0];
            red_r[wn * 128 + wr + mi * 16 + g + 8] = rowAcc[mi][1];
        }
    }
    __syncthreads();
    if (tid < 128) {
        float rs = red_r[tid] + red_r[128 + tid] + red_r[256 + tid] + red_r[384 + tid];
        g_partial_r[rem * N2 + row0 + tid] = rs;
    }
}

// ============================================================================
// rowloss + loss
// ============================================================================
__global__ void rowloss_kernel()
{
    const int i = blockIdx.x * 128 + threadIdx.x;
    const int b = i >> 7;
    const int ng = (64 - b + 3) >> 2;
    float se = 0.f;
    for (int t = 0; t < ng; t++) se += g_partial_r[t * N2 + i];
    for (int x = 0; x <= b; x++) se += g_partial_c[x * N2 + i];
    g_rowloss[i] = logf(se) - g_pos[i];
}

__global__ void loss_kernel(float* __restrict__ out)
{
    __shared__ float sh[256];
    float s = 0.f;
    for (int i = threadIdx.x; i < N2; i += 256) s += g_rowloss[i];
    sh[threadIdx.x] = s;
    __syncthreads();
    for (int o = 128; o; o >>= 1) {
        if (threadIdx.x < o) sh[threadIdx.x] += sh[threadIdx.x + o];
        __syncthreads();
    }
    if (threadIdx.x == 0) out[0] = sh[0] * (1.0f / N2);
}

// ============================================================================
extern "C" void kernel_launch(void* const* d_in, const int* in_sizes, int n_in,
                              void* d_out, int out_size)
{
    const float* h1    = (const float*)d_in[0];
    const float* h2    = (const float*)d_in[1];
    const float* W1    = (const float*)d_in[2];
    const float* b1    = (const float*)d_in[3];
    const float* gamma = (const float*)d_in[4];
    const float* beta  = (const float*)d_in[5];
    const float* W2    = (const float*)d_in[6];
    const float* b2    = (const float*)d_in[7];
    float* out = (float*)d_out;

    cudaFuncSetAttribute(sim_kernel, cudaFuncAttributeMaxDynamicSharedMemorySize,
                         SIM_SMEM_BYTES);

    gemm1_kernel<<<dim3(N2 / 128, D_HID / 64), 256>>>(h1, h2, W1, b1);
    bn_part_kernel<<<dim3(4, 32), 256>>>();
    bn_final_kernel<<<4, 256>>>(gamma, beta);
    gemm2_kernel<<<dim3(N2 / 64, 2), 256>>>(W2);
    norm_kernel<<<BATCH / 4, 256>>>(b2, out);
    sim_kernel<<<SIM_GROUPS, 256, SIM_SMEM_BYTES>>>();
    rowloss_kernel<<<N2 / 128, 128>>>();
    loss_kernel<<<1, 256>>>(out);
}

// round 9
// speedup vs baseline: 2.3237x; 1.0023x over previous
#include <cuda_runtime.h>
#include <cuda_bf16.h>
#include <math.h>
#include <stdint.h>

// Problem dims
#define BATCH   4096
#define D_IN    192
#define D_HID   512
#define D_OUT   128
#define N2      8192            // 2*BATCH
#define TEMP_INV 2.0f           // 1/0.5
#define BN_EPS   1e-5f

// Sim symmetric-tiling config
#define SIM_GROUPS 544
#define SIM_MAX_T  16

// ---------------- scratch (device globals; no allocation allowed) ----------
__device__ float g_y[N2 * D_HID];          // 16 MB
__device__ float g_bn_ps[64 * 512];        // per-row-panel column sums
__device__ float g_bn_pq[64 * 512];        // per-row-panel column sumsq
__device__ float g_bn_scale[2 * D_HID];
__device__ float g_bn_bias[2 * D_HID];
__device__ float g_zp0[N2 * D_OUT];        // gemm2 split-K partials
__device__ float g_zp1[N2 * D_OUT];
__device__ float g_zp2[N2 * D_OUT];
__device__ float g_zp3[N2 * D_OUT];
__device__ float g_z[N2 * D_OUT];
__device__ __nv_bfloat16 g_zh[N2 * D_OUT];
__device__ float g_partial_r[SIM_MAX_T * N2];
__device__ float g_partial_c[64 * N2];
__device__ float g_rowloss[N2];
__device__ float g_pos[N2];

// ============================================================================
// helpers
// ============================================================================
__device__ __forceinline__ float to_tf32(float x) {
    float r;
    asm("cvt.rna.tf32.f32 %0, %1;" : "=f"(r) : "f"(x));
    return r;
}
__device__ __forceinline__ void mma_tf32(float* c, const uint32_t* a, const uint32_t* b)
{
    asm volatile(
        "mma.sync.aligned.m16n8k8.row.col.f32.tf32.tf32.f32 "
        "{%0,%1,%2,%3}, {%4,%5,%6,%7}, {%8,%9}, {%0,%1,%2,%3};"
        : "+f"(c[0]), "+f"(c[1]), "+f"(c[2]), "+f"(c[3])
        : "r"(a[0]), "r"(a[1]), "r"(a[2]), "r"(a[3]), "r"(b[0]), "r"(b[1]));
}
__device__ __forceinline__ void mma_bf16(float* c, const uint32_t* a, const uint32_t* b)
{
    asm volatile(
        "mma.sync.aligned.m16n8k16.row.col.f32.bf16.bf16.f32 "
        "{%0,%1,%2,%3}, {%4,%5,%6,%7}, {%8,%9}, {%0,%1,%2,%3};"
        : "+f"(c[0]), "+f"(c[1]), "+f"(c[2]), "+f"(c[3])
        : "r"(a[0]), "r"(a[1]), "r"(a[2]), "r"(a[3]), "r"(b[0]), "r"(b[1]));
}
__device__ __forceinline__ uint32_t smem_u32(const void* p) {
    uint32_t a;
    asm("{ .reg .u64 t; cvta.to.shared.u64 t, %1; cvt.u32.u64 %0, t; }" : "=r"(a) : "l"(p));
    return a;
}
#define CP_ASYNC16(dst, src) \
    asm volatile("cp.async.cg.shared.global [%0], [%1], 16;" :: "r"(dst), "l"(src))
#define CP_COMMIT()  asm volatile("cp.async.commit_group;" ::: "memory")
#define CP_WAIT0()   asm volatile("cp.async.wait_group 0;" ::: "memory")
#define CP_WAIT1()   asm volatile("cp.async.wait_group 1;" ::: "memory")

// ============================================================================
// GEMM1 (tf32, reg-prefetch pipelined): y = X @ W1^T + b1.
// Tile 128x64, grid (64, 8). Epilogue fuses BN column sum/sumsq partials.
// ============================================================================
#define G1_AS 36
__global__ __launch_bounds__(256, 2) void gemm1_kernel(
    const float* __restrict__ h1, const float* __restrict__ h2,
    const float* __restrict__ W1, const float* __restrict__ b1)
{
    __shared__ float As[128][G1_AS];
    __shared__ float Bs[64][G1_AS];
    const int tid  = threadIdx.x;
    const int wid  = tid >> 5, lane = tid & 31;
    const int g    = lane >> 2, tq = lane & 3;
    const int wr   = (wid >> 1) * 32;
    const int wc   = (wid & 1) * 32;
    const int row0 = blockIdx.x * 128;
    const int col0 = blockIdx.y * 64;
    const float* A = (row0 < BATCH) ? h1 : h2;
    const int arow0 = (row0 < BATCH) ? row0 : (row0 - BATCH);
    const float4* A4  = (const float4*)A;
    const float4* W14 = (const float4*)W1;

    // prefetch k-tile 0 into registers
    float4 va[4], vb[2];
    #pragma unroll
    for (int it = 0; it < 4; it++) {
        int idx = tid + it * 256; int r = idx >> 3, c = idx & 7;
        va[it] = A4[(arow0 + r) * 48 + c];
    }
    #pragma unroll
    for (int it = 0; it < 2; it++) {
        int idx = tid + it * 256; int r = idx >> 3, c = idx & 7;
        vb[it] = W14[(col0 + r) * 48 + c];
    }

    float acc[2][4][4] = {};

    for (int kt = 0; kt < D_IN; kt += 32) {
        // store prefetched regs -> smem (tf32 cvt)
        #pragma unroll
        for (int it = 0; it < 4; it++) {
            int idx = tid + it * 256; int r = idx >> 3, c = idx & 7;
            float* d = &As[r][c * 4];
            d[0] = to_tf32(va[it].x); d[1] = to_tf32(va[it].y);
            d[2] = to_tf32(va[it].z); d[3] = to_tf32(va[it].w);
        }
        #pragma unroll
        for (int it = 0; it < 2; it++) {
            int idx = tid + it * 256; int r = idx >> 3, c = idx & 7;
            float* d = &Bs[r][c * 4];
            d[0] = to_tf32(vb[it].x); d[1] = to_tf32(vb[it].y);
            d[2] = to_tf32(vb[it].z); d[3] = to_tf32(vb[it].w);
        }
        __syncthreads();
        // issue next k-tile loads (overlap with MMA below)
        if (kt + 32 < D_IN) {
            const int kt4 = (kt + 32) >> 2;
            #pragma unroll
            for (int it = 0; it < 4; it++) {
                int idx = tid + it * 256; int r = idx >> 3, c = idx & 7;
                va[it] = A4[(arow0 + r) * 48 + kt4 + c];
            }
            #pragma unroll
            for (int it = 0; it < 2; it++) {
                int idx = tid + it * 256; int r = idx >> 3, c = idx & 7;
                vb[it] = W14[(col0 + r) * 48 + kt4 + c];
            }
        }
        #pragma unroll
        for (int kk = 0; kk < 4; kk++) {
            uint32_t a[2][4], b[4][2];
            #pragma unroll
            for (int mi = 0; mi < 2; mi++) {
                const uint32_t* ap = (const uint32_t*)&As[wr + mi * 16 + g][kk * 8 + tq];
                a[mi][0] = ap[0];
                a[mi][1] = ap[8 * G1_AS];
                a[mi][2] = ap[4];
                a[mi][3] = ap[8 * G1_AS + 4];
            }
            #pragma unroll
            for (int ni = 0; ni < 4; ni++) {
                const uint32_t* bp = (const uint32_t*)&Bs[wc + ni * 8 + g][kk * 8 + tq];
                b[ni][0] = bp[0];
                b[ni][1] = bp[4];
            }
            #pragma unroll
            for (int mi = 0; mi < 2; mi++)
                #pragma unroll
                for (int ni = 0; ni < 4; ni++)
                    mma_tf32(acc[mi][ni], a[mi], b[ni]);
        }
        __syncthreads();
    }

    // Epilogue: write y (+bias) and accumulate per-column sum / sumsq
    float s_c[4][2] = {}, q_c[4][2] = {};
    #pragma unroll
    for (int mi = 0; mi < 2; mi++) {
        const int r0 = row0 + wr + mi * 16 + g;
        #pragma unroll
        for (int ni = 0; ni < 4; ni++) {
            const int c0 = col0 + wc + ni * 8 + tq * 2;
            float v0 = acc[mi][ni][0] + b1[c0];
            float v1 = acc[mi][ni][1] + b1[c0 + 1];
            float v2 = acc[mi][ni][2] + b1[c0];
            float v3 = acc[mi][ni][3] + b1[c0 + 1];
            g_y[r0 * D_HID + c0]           = v0;
            g_y[r0 * D_HID + c0 + 1]       = v1;
            g_y[(r0 + 8) * D_HID + c0]     = v2;
            g_y[(r0 + 8) * D_HID + c0 + 1] = v3;
            s_c[ni][0] += v0 + v2;          s_c[ni][1] += v1 + v3;
            q_c[ni][0] += v0 * v0 + v2 * v2; q_c[ni][1] += v1 * v1 + v3 * v3;
        }
    }
    // reduce over g lanes (rows within warp-row group)
    #pragma unroll
    for (int ni = 0; ni < 4; ni++)
        #pragma unroll
        for (int h = 0; h < 2; h++) {
            float s = s_c[ni][h], q = q_c[ni][h];
            s += __shfl_xor_sync(0xffffffffu, s, 4);
            s += __shfl_xor_sync(0xffffffffu, s, 8);
            s += __shfl_xor_sync(0xffffffffu, s, 16);
            q += __shfl_xor_sync(0xffffffffu, q, 4);
            q += __shfl_xor_sync(0xffffffffu, q, 8);
            q += __shfl_xor_sync(0xffffffffu, q, 16);
            s_c[ni][h] = s; q_c[ni][h] = q;
        }
    __syncthreads();                 // As free
    float* red = (float*)As;         // s: [4 rg][64], q at +256
    if (lane < 4) {                  // g==0, tq=lane
        const int rg = wid >> 1;
        #pragma unroll
        for (int ni = 0; ni < 4; ni++) {
            int lc = wc + ni * 8 + tq * 2;
            red[rg * 64 + lc]           = s_c[ni][0];
            red[rg * 64 + lc + 1]       = s_c[ni][1];
            red[256 + rg * 64 + lc]     = q_c[ni][0];
            red[256 + rg * 64 + lc + 1] = q_c[ni][1];
        }
    }
    __syncthreads();
    if (tid < 64) {
        float s = red[tid] + red[64 + tid] + red[128 + tid] + red[192 + tid];
        float q = red[256 + tid] + red[320 + tid] + red[384 + tid] + red[448 + tid];
        g_bn_ps[blockIdx.x * 512 + col0 + tid] = s;
        g_bn_pq[blockIdx.x * 512 + col0 + tid] = q;
    }
}

// ============================================================================
// BN finalize: sum 32 row-panel partials per head. grid 4, block 256.
// ============================================================================
__global__ void bn_final_kernel(const float* __restrict__ gamma,
                                const float* __restrict__ beta)
{
    const int c    = blockIdx.x * 256 + threadIdx.x;   // 0..1023
    const int head = c >> 9;
    const int col  = c & 511;
    float s = 0.f, q = 0.f;
    #pragma unroll
    for (int k = 0; k < 32; k++) {
        int p = head * 32 + k;
        s += g_bn_ps[p * 512 + col];
        q += g_bn_pq[p * 512 + col];
    }
    float mean = s * (1.0f / BATCH);
    float var  = q * (1.0f / BATCH) - mean * mean;
    float a = gamma[col] * rsqrtf(var + BN_EPS);
    g_bn_scale[c] = a;
    g_bn_bias[c]  = beta[col] - mean * a;
}

// ============================================================================
// GEMM2 (tf32, split-K=4, reg-prefetch pipelined).
// Tile 64x128, grid (128, 4). Partials -> g_zp0..3.
// ============================================================================
__global__ __launch_bounds__(256, 2) void gemm2_kernel(const float* __restrict__ W2)
{
    __shared__ float As[64][G1_AS];
    __shared__ float Bs[128][G1_AS];
    const int tid  = threadIdx.x;
    const int wid  = tid >> 5, lane = tid & 31;
    const int g    = lane >> 2, tq = lane & 3;
    const int wr   = (wid >> 2) * 32;
    const int wc   = (wid & 3) * 32;
    const int row0 = blockIdx.x * 64;
    const int ks   = blockIdx.y * 128;
    const int head = row0 >> 12;
    const float4* sc4 = (const float4*)(g_bn_scale + head * D_HID);
    const float4* bi4 = (const float4*)(g_bn_bias  + head * D_HID);
    const float4* Y4  = (const float4*)g_y;
    const float4* W24 = (const float4*)W2;
    float* outp = (blockIdx.y == 0) ? g_zp0 : (blockIdx.y == 1) ? g_zp1
                : (blockIdx.y == 2) ? g_zp2 : g_zp3;

    // prefetch first k-tile
    float4 va[2], vb[4];
    {
        const int kt4 = ks >> 2;
        #pragma unroll
        for (int it = 0; it < 2; it++) {
            int idx = tid + it * 256; int r = idx >> 3, c = idx & 7;
            va[it] = Y4[(row0 + r) * 128 + kt4 + c];
        }
        #pragma unroll
        for (int it = 0; it < 4; it++) {
            int idx = tid + it * 256; int r = idx >> 3, c = idx & 7;
            vb[it] = W24[r * 128 + kt4 + c];
        }
    }

    float acc[2][4][4] = {};

    for (int kt = ks; kt < ks + 128; kt += 32) {
        const int kt4 = kt >> 2;
        // store regs -> smem with BN+ReLU+cvt (A) / cvt (B)
        #pragma unroll
        for (int it = 0; it < 2; it++) {
            int idx = tid + it * 256; int r = idx >> 3, c = idx & 7;
            float4 s4 = sc4[kt4 + c];
            float4 o4 = bi4[kt4 + c];
            float* d = &As[r][c * 4];
            d[0] = to_tf32(fmaxf(fmaf(va[it].x, s4.x, o4.x), 0.f));
            d[1] = to_tf32(fmaxf(fmaf(va[it].y, s4.y, o4.y), 0.f));
            d[2] = to_tf32(fmaxf(fmaf(va[it].z, s4.z, o4.z), 0.f));
            d[3] = to_tf32(fmaxf(fmaf(va[it].w, s4.w, o4.w), 0.f));
        }
        #pragma unroll
        for (int it = 0; it < 4; it++) {
            int idx = tid + it * 256; int r = idx >> 3, c = idx & 7;
            float* d = &Bs[r][c * 4];
            d[0] = to_tf32(vb[it].x); d[1] = to_tf32(vb[it].y);
            d[2] = to_tf32(vb[it].z); d[3] = to_tf32(vb[it].w);
        }
        __syncthreads();
        if (kt + 32 < ks + 128) {
            const int nt4 = (kt + 32) >> 2;
            #pragma unroll
            for (int it = 0; it < 2; it++) {
                int idx = tid + it * 256; int r = idx >> 3, c = idx & 7;
                va[it] = Y4[(row0 + r) * 128 + nt4 + c];
            }
            #pragma unroll
            for (int it = 0; it < 4; it++) {
                int idx = tid + it * 256; int r = idx >> 3, c = idx & 7;
                vb[it] = W24[r * 128 + nt4 + c];
            }
        }
        #pragma unroll
        for (int kk = 0; kk < 4; kk++) {
            uint32_t a[2][4], b[4][2];
            #pragma unroll
            for (int mi = 0; mi < 2; mi++) {
                const uint32_t* ap = (const uint32_t*)&As[wr + mi * 16 + g][kk * 8 + tq];
                a[mi][0] = ap[0];
                a[mi][1] = ap[8 * G1_AS];
                a[mi][2] = ap[4];
                a[mi][3] = ap[8 * G1_AS + 4];
            }
            #pragma unroll
            for (int ni = 0; ni < 4; ni++) {
                const uint32_t* bp = (const uint32_t*)&Bs[wc + ni * 8 + g][kk * 8 + tq];
                b[ni][0] = bp[0];
                b[ni][1] = bp[4];
            }
            #pragma unroll
            for (int mi = 0; mi < 2; mi++)
                #pragma unroll
                for (int ni = 0; ni < 4; ni++)
                    mma_tf32(acc[mi][ni], a[mi], b[ni]);
        }
        __syncthreads();
    }
    #pragma unroll
    for (int mi = 0; mi < 2; mi++) {
        const int r0 = row0 + wr + mi * 16 + g;
        #pragma unroll
        for (int ni = 0; ni < 4; ni++) {
            const int c0 = wc + ni * 8 + tq * 2;
            outp[r0 * D_OUT + c0]           = acc[mi][ni][0];
            outp[r0 * D_OUT + c0 + 1]       = acc[mi][ni][1];
            outp[(r0 + 8) * D_OUT + c0]     = acc[mi][ni][2];
            outp[(r0 + 8) * D_OUT + c0 + 1] = acc[mi][ni][3];
        }
    }
}

// ============================================================================
// norm + pos fused (sums 4 split-K partials + bias).
// ============================================================================
__global__ void norm_kernel(const float* __restrict__ b2, float* __restrict__ out)
{
    const int tid  = threadIdx.x;
    const int wid  = tid >> 5, lane = tid & 31;
    const int pi   = blockIdx.x * 4 + (wid & 3);
    const int row  = (wid < 4) ? pi : pi + BATCH;

    const float4 p0 = ((const float4*)(g_zp0 + row * D_OUT))[lane];
    const float4 p1 = ((const float4*)(g_zp1 + row * D_OUT))[lane];
    const float4 p2 = ((const float4*)(g_zp2 + row * D_OUT))[lane];
    const float4 p3 = ((const float4*)(g_zp3 + row * D_OUT))[lane];
    const float4 bb = ((const float4*)b2)[lane];
    float4 v = make_float4(p0.x + p1.x + p2.x + p3.x + bb.x,
                           p0.y + p1.y + p2.y + p3.y + bb.y,
                           p0.z + p1.z + p2.z + p3.z + bb.z,
                           p0.w + p1.w + p2.w + p3.w + bb.w);
    float s = v.x * v.x + v.y * v.y + v.z * v.z + v.w * v.w;
    #pragma unroll
    for (int o = 16; o; o >>= 1) s += __shfl_xor_sync(0xffffffffu, s, o);
    const float inv = 1.0f / fmaxf(sqrtf(s), 1e-12f);
    float4 z = make_float4(v.x * inv, v.y * inv, v.z * inv, v.w * inv);
    ((float4*)(g_z + row * D_OUT))[lane] = z;
    __nv_bfloat162* zh2 = (__nv_bfloat162*)(g_zh + row * D_OUT);
    zh2[lane * 2 + 0] = __nv_bfloat162(__float2bfloat16(z.x), __float2bfloat16(z.y));
    zh2[lane * 2 + 1] = __nv_bfloat162(__float2bfloat16(z.z), __float2bfloat16(z.w));
    float* o4 = out + 1 + row * D_OUT + lane * 4;
    o4[0] = z.x; o4[1] = z.y; o4[2] = z.z; o4[3] = z.w;

    __shared__ float4 zsh[4][32];
    if (wid >= 4) zsh[wid - 4][lane] = z;
    __syncthreads();
    if (wid < 4) {
        float4 p = zsh[wid][lane];
        float d = z.x * p.x + z.y * p.y + z.z * p.z + z.w * p.w;
        #pragma unroll
        for (int o = 16; o; o >>= 1) d += __shfl_xor_sync(0xffffffffu, d, o);
        if (lane == 0) {
            float pv = d * TEMP_INV;
            g_pos[pi] = pv;
            g_pos[pi + BATCH] = pv;
        }
    }
}

// ============================================================================
// Symmetric sim (unchanged from R8): grouped, cp.async double-buffered B.
// ============================================================================
#define SIM_TILE_STRIDE 136
#define SIM_TILE_BYTES  (128 * SIM_TILE_STRIDE * 2)
#define SIM_SMEM_BYTES  (3 * SIM_TILE_BYTES + 1024)   // 105472

__global__ __launch_bounds__(256, 2) void sim_kernel()
{
    int rem = blockIdx.x, bi = 0;
    for (;;) {
        int cnt = (64 - bi + 3) >> 2;
        if (rem < cnt) break;
        rem -= cnt; bi++;
    }
    const int bj0  = bi + rem * 4;
    const int jend = (bj0 + 4 < 64) ? bj0 + 4 : 64;

    extern __shared__ __nv_bfloat16 smem_bf[];
    __nv_bfloat16* As  = smem_bf;
    __nv_bfloat16* Bs0 = smem_bf + 128 * SIM_TILE_STRIDE;
    __nv_bfloat16* Bs1 = Bs0 + 128 * SIM_TILE_STRIDE;
    float* red_c = (float*)(Bs1 + 128 * SIM_TILE_STRIDE);
    const uint32_t bs0_u = smem_u32(Bs0);
    const uint32_t bs1_u = smem_u32(Bs1);

    const int tid  = threadIdx.x;
    const int wid  = tid >> 5, lane = tid & 31;
    const int g    = lane >> 2, tq = lane & 3;
    const int wr   = (wid >> 2) * 64;
    const int wn   = wid & 3;
    const int wc   = wn * 32;
    const int row0 = bi * 128;

    {
        const char* src = (const char*)(g_zh + bj0 * 128 * D_OUT);
        for (int idx = tid; idx < 2048; idx += 256) {
            int r = idx >> 4, c = idx & 15;
            CP_ASYNC16(bs0_u + (uint32_t)(r * 17 + c) * 16, src + idx * 16);
        }
        CP_COMMIT();
    }
    {
        const uint4* src = (const uint4*)(g_zh + row0 * D_OUT);
        uint4* dst = (uint4*)As;
        for (int idx = tid; idx < 2048; idx += 256) {
            int r = idx >> 4, c = idx & 15;
            dst[r * 17 + c] = src[idx];
        }
    }

    float rowAcc[4][2] = {};
    int buf = 0;

    for (int bj = bj0; bj < jend; bj++) {
        const bool diag = (bj == bi);
        const bool has_next = (bj + 1 < jend);
        if (has_next) {
            const char* src = (const char*)(g_zh + (bj + 1) * 128 * D_OUT);
            uint32_t dst_u = buf ? bs0_u : bs1_u;
            for (int idx = tid; idx < 2048; idx += 256) {
                int r = idx >> 4, c = idx & 15;
                CP_ASYNC16(dst_u + (uint32_t)(r * 17 + c) * 16, src + idx * 16);
            }
            CP_COMMIT();
            CP_WAIT1();
        } else {
            CP_WAIT0();
        }
        __syncthreads();

        const __nv_bfloat16* Bs = buf ? Bs1 : Bs0;

        float acc[4][4][4] = {};
        #pragma unroll
        for (int kk = 0; kk < 128; kk += 16) {
            uint32_t a[4][4], b[4][2];
            #pragma unroll
            for (int mi = 0; mi < 4; mi++) {
                const __nv_bfloat16* ap = As + (wr + mi * 16 + g) * SIM_TILE_STRIDE + kk + tq * 2;
                a[mi][0] = *(const uint32_t*)ap;
                a[mi][1] = *(const uint32_t*)(ap + 8 * SIM_TILE_STRIDE);
                a[mi][2] = *(const uint32_t*)(ap + 8);
                a[mi][3] = *(const uint32_t*)(ap + 8 * SIM_TILE_STRIDE + 8);
            }
            #pragma unroll
            for (int ni = 0; ni < 4; ni++) {
                const __nv_bfloat16* bp = Bs + (wc + ni * 8 + g) * SIM_TILE_STRIDE + kk + tq * 2;
                b[ni][0] = *(const uint32_t*)bp;
                b[ni][1] = *(const uint32_t*)(bp + 8);
            }
            #pragma unroll
            for (int mi = 0; mi < 4; mi++)
                #pragma unroll
                for (int ni = 0; ni < 4; ni++)
                    mma_bf16(acc[mi][ni], a[mi], b[ni]);
        }

        float colAcc[4][2] = {};
        #pragma unroll
        for (int mi = 0; mi < 4; mi++) {
            const int lr0 = wr + mi * 16 + g;
            const int lr1 = lr0 + 8;
            #pragma unroll
            for (int ni = 0; ni < 4; ni++) {
                const int lj0 = wc + ni * 8 + tq * 2;
                float e00 = __expf(2.0f * acc[mi][ni][0]);
                float e01 = __expf(2.0f * acc[mi][ni][1]);
                float e10 = __expf(2.0f * acc[mi][ni][2]);
                float e11 = __expf(2.0f * acc[mi][ni][3]);
                if (diag) {
                    if (lj0     == lr0) e00 = 0.f;
                    if (lj0 + 1 == lr0) e01 = 0.f;
                    if (lj0     == lr1) e10 = 0.f;
                    if (lj0 + 1 == lr1) e11 = 0.f;
                }
                rowAcc[mi][0] += e00 + e01;
                rowAcc[mi][1] += e10 + e11;
                colAcc[ni][0] += e00 + e10;
                colAcc[ni][1] += e01 + e11;
            }
        }

        #pragma unroll
        for (int ni = 0; ni < 4; ni++)
            #pragma unroll
            for (int h = 0; h < 2; h++) {
                float s = colAcc[ni][h];
                s += __shfl_xor_sync(0xffffffffu, s, 4);
                s += __shfl_xor_sync(0xffffffffu, s, 8);
                s += __shfl_xor_sync(0xffffffffu, s, 16);
                colAcc[ni][h] = s;
            }
        if (g == 0) {
            #pragma unroll
            for (int ni = 0; ni < 4; ni++) {
                red_c[wid * 32 + ni * 8 + tq * 2]     = colAcc[ni][0];
                red_c[wid * 32 + ni * 8 + tq * 2 + 1] = colAcc[ni][1];
            }
        }
        __syncthreads();
        if (tid < 128) {
            int wgrp = tid >> 5, jl = tid & 31;
            float cs = diag ? 0.f : (red_c[wgrp * 32 + jl] + red_c[(wgrp + 4) * 32 + jl]);
            g_partial_c[bi * N2 + bj * 128 + tid] = cs;
        }
        buf ^= 1;
    }

    #pragma unroll
    for (int mi = 0; mi < 4; mi++)
        #pragma unroll
        for (int h = 0; h < 2; h++) {
            float s = rowAcc[mi][h];
            s += __shfl_xor_sync(0xffffffffu, s, 1);
            s += __shfl_xor_sync(0xffffffffu, s, 2);
            rowAcc[mi][h] = s;
        }
    __syncthreads();
    float* red_r = (float*)smem_bf;
    if (tq == 0) {
        #pragma unroll
        for (int mi = 0; mi < 4; mi++) {
            red_r[wn * 128 + wr + mi * 16 + g]     = rowAcc[mi][0];
            red_r[wn * 128 + wr + mi * 16 + g + 8] = rowAcc[mi][1];
        }
    }
    __syncthreads();
    if (tid < 128) {
        float rs = red_r[tid] + red_r[128 + tid] + red_r[256 + tid] + red_r[384 + tid];
        g_partial_r[rem * N2 + row0 + tid] = rs;
    }
}

// ============================================================================
// rowloss + loss
// ============================================================================
__global__ void rowloss_kernel()
{
    const int i = blockIdx.x * 128 + threadIdx.x;
    const int b = i >> 7;
    const int ng = (64 - b + 3) >> 2;
    float se = 0.f;
    for (int t = 0; t < ng; t++) se += g_partial_r[t * N2 + i];
    for (int x = 0; x <= b; x++) se += g_partial_c[x * N2 + i];
    g_rowloss[i] = logf(se) - g_pos[i];
}

__global__ void loss_kernel(float* __restrict__ out)
{
    __shared__ float sh[256];
    float s = 0.f;
    for (int i = threadIdx.x; i < N2; i += 256) s += g_rowloss[i];
    sh[threadIdx.x] = s;
    __syncthreads();
    for (int o = 128; o; o >>= 1) {
        if (threadIdx.x < o) sh[threadIdx.x] += sh[threadIdx.x + o];
        __syncthreads();
    }
    if (threadIdx.x == 0) out[0] = sh[0] * (1.0f / N2);
}

// ============================================================================
extern "C" void kernel_launch(void* const* d_in, const int* in_sizes, int n_in,
                              void* d_out, int out_size)
{
    const float* h1    = (const float*)d_in[0];
    const float* h2    = (const float*)d_in[1];
    const float* W1    = (const float*)d_in[2];
    const float* b1    = (const float*)d_in[3];
    const float* gamma = (const float*)d_in[4];
    const float* beta  = (const float*)d_in[5];
    const float* W2    = (const float*)d_in[6];
    const float* b2    = (const float*)d_in[7];
    float* out = (float*)d_out;

    cudaFuncSetAttribute(sim_kernel, cudaFuncAttributeMaxDynamicSharedMemorySize,
                         SIM_SMEM_BYTES);

    gemm1_kernel<<<dim3(N2 / 128, D_HID / 64), 256>>>(h1, h2, W1, b1);
    bn_final_kernel<<<4, 256>>>(gamma, beta);
    gemm2_kernel<<<dim3(N2 / 64, 4), 256>>>(W2);
    norm_kernel<<<BATCH / 4, 256>>>(b2, out);
    sim_kernel<<<SIM_GROUPS, 256, SIM_SMEM_BYTES>>>();
    rowloss_kernel<<<N2 / 128, 128>>>();
    loss_kernel<<<1, 256>>>(out);
}